// round 12
// baseline (speedup 1.0000x reference)
#include <cuda_runtime.h>
#define KNB 16
typedef unsigned u32;

__device__ __align__(256) float g_fA[20096 * 128];
__device__ __align__(256) float g_fB[20096 * 128];
__device__ __align__(256) float g_gX[20096 * 640];
__device__ __align__(256) float g_Wp[512 * 128];

__device__ __forceinline__ float tanha(float x) {
    float r; asm("tanh.approx.f32 %0, %1;" : "=f"(r) : "f"(x)); return r;
}
__device__ __forceinline__ float siga(float x) {
    return fmaf(tanha(0.5f * x), 0.5f, 0.5f);
}
__device__ __forceinline__ u32 tf32r(float f) {
    u32 r; asm("cvt.rna.tf32.f32 %0, %1;" : "=r"(r) : "f"(f)); return r;
}
__device__ __forceinline__ uint4 tf32x4(float4 v) {
    return make_uint4(tf32r(v.x), tf32r(v.y), tf32r(v.z), tf32r(v.w));
}
__device__ __forceinline__ void mma8(float* d, const u32* a, const u32* b) {
    asm volatile("mma.sync.aligned.m16n8k8.row.col.f32.tf32.tf32.f32 "
        "{%0,%1,%2,%3},{%4,%5,%6,%7},{%8,%9},{%0,%1,%2,%3};"
        : "+f"(d[0]), "+f"(d[1]), "+f"(d[2]), "+f"(d[3])
        : "r"(a[0]), "r"(a[1]), "r"(a[2]), "r"(a[3]), "r"(b[0]), "r"(b[1]));
}
__device__ __forceinline__ u32 smem_u32(const void* p) {
    u32 a; asm("{ .reg .u64 t; cvta.to.shared.u64 t, %1; cvt.u32.u64 %0, t; }" : "=r"(a) : "l"(p)); return a;
}
__device__ __forceinline__ void cpa16(u32 dst, const void* src) {
    asm volatile("cp.async.cg.shared.global [%0], [%1], 16;" :: "r"(dst), "l"(src));
}
__device__ __forceinline__ void cpa_commit() { asm volatile("cp.async.commit_group;"); }
__device__ __forceinline__ void cpa_wait0()  { asm volatile("cp.async.wait_group 0;" ::: "memory"); }

// Gate-column permutation (see R10): thread (gq,tq) of warp ng owns all 4 gates
// of its units directly in its MMA output registers.
__device__ __forceinline__ int gmap(int c, int DIN) {
    int blk = c >> 5, w5 = c & 31;
    int nt = w5 >> 3, tq = (w5 >> 1) & 3, e = w5 & 1;
    return (2 * (nt & 1) + e) * DIN + blk * 8 + (nt >> 1) * 4 + tq;
}

__global__ void build_feat0(const float* __restrict__ p, float* __restrict__ f0, int nN) {
    int i = blockIdx.x * blockDim.x + threadIdx.x;
    if (i >= nN * 64) return;
    int node = i >> 6, k = i & 63;
    f0[i] = (k == 0) ? (16.0f / (float)nN) : p[node * 63 + (k - 1)];
}

// pre-pack Whh: tf32-rounded, gmap-permuted rows, contiguous DIN-float rows
__global__ void pack_k(const float* __restrict__ Whh, float* __restrict__ Wp, int DIN) {
    int K4 = DIN >> 2;
    int e = blockIdx.x * 256 + threadIdx.x;
    if (e >= 4 * DIN * K4) return;
    int row = e / K4, c4 = e % K4;
    ((uint4*)Wp)[e] = tf32x4(((const float4*)Whh)[gmap(row, DIN) * K4 + c4]);
}

// ---------------- precompute: gX[n] = feat[n] @ [Wih(permuted) | Wself]^T + bias ----------------
template <int DIN, int DOUT>
__global__ __launch_bounds__(384, 1)
void pre_k(const float* __restrict__ feat,
           const float* __restrict__ Wih, const float* __restrict__ bih,
           const float* __restrict__ bhh, const float* __restrict__ Wself,
           const float* __restrict__ bo, float* __restrict__ gX, int nN)
{
    constexpr int TM = 144, NT = 384, K4 = DIN / 4, SXA = DIN + 4, W = 4 * DIN + DOUT;
    extern __shared__ float sm[];
    float* Xs = sm;
    float* Ws = sm + TM * SXA;
    float* CB = Ws + 128 * SXA;

    const int tid = threadIdx.x, lane = tid & 31, w = tid >> 5;
    const int gq = lane >> 2, tq = lane & 3, mg = w % 3, ng = w / 3, MB = 48 * mg;
    const int node0 = blockIdx.x * TM;
    const float4* fin4 = (const float4*)feat;
    const float4* Wi4 = (const float4*)Wih;
    const float4* Wsf4 = (const float4*)Wself;

    for (int e = tid; e < 4 * DIN; e += NT) {
        int sr = gmap(e, DIN);
        CB[e] = bih[sr] + bhh[sr];
    }
    for (int e = tid; e < DOUT; e += NT) CB[4 * DIN + e] = bo[e];
    for (int e = tid; e < TM * K4; e += NT) {
        int row = e / K4, c4 = e % K4;
        int nd = node0 + row; if (nd >= nN) nd = nN - 1;
        ((uint4*)(Xs + row * SXA))[c4] = tf32x4(fin4[nd * K4 + c4]);
    }
    const float* pA0 = Xs + (MB + gq) * SXA + tq;

    for (int c0 = 0; c0 < W; c0 += 128) {
        const int CR = (W - c0 < 128) ? (W - c0) : 128;
        const int NTW = CR / 32, CG = CR / 4;
        __syncthreads();
        for (int e = tid; e < CR * K4; e += NT) {
            int r = e / K4, c4 = e % K4;
            int gc = c0 + r;
            float4 v = (gc < 4 * DIN) ? Wi4[gmap(gc, DIN) * K4 + c4]
                                      : Wsf4[(gc - 4 * DIN) * K4 + c4];
            ((uint4*)(Ws + r * SXA))[c4] = tf32x4(v);
        }
        __syncthreads();
        float D[3][4][4];
        for (int nt = 0; nt < NTW; nt++) {
            float b0 = CB[c0 + CG * ng + 8 * nt + 2 * tq];
            float b1 = CB[c0 + CG * ng + 8 * nt + 2 * tq + 1];
#pragma unroll
            for (int mi = 0; mi < 3; mi++) {
                D[mi][nt][0] = b0; D[mi][nt][1] = b1;
                D[mi][nt][2] = b0; D[mi][nt][3] = b1;
            }
        }
#pragma unroll 4
        for (int k0 = 0; k0 < DIN; k0 += 8) {
            u32 a[3][4], b[4][2];
#pragma unroll
            for (int mi = 0; mi < 3; mi++) {
                const float* pa = pA0 + 16 * mi * SXA + k0;
                a[mi][0] = __float_as_uint(pa[0]);
                a[mi][1] = __float_as_uint(pa[8 * SXA]);
                a[mi][2] = __float_as_uint(pa[4]);
                a[mi][3] = __float_as_uint(pa[8 * SXA + 4]);
            }
            for (int nt = 0; nt < NTW; nt++) {
                const float* pb = Ws + (CG * ng + 8 * nt + gq) * SXA + tq + k0;
                b[nt][0] = __float_as_uint(pb[0]);
                b[nt][1] = __float_as_uint(pb[4]);
#pragma unroll
                for (int mi = 0; mi < 3; mi++) mma8(D[mi][nt], a[mi], b[nt]);
            }
        }
        for (int nt = 0; nt < NTW; nt++) {
            int col = c0 + CG * ng + 8 * nt + 2 * tq;
#pragma unroll
            for (int mi = 0; mi < 3; mi++) {
                int r0 = node0 + MB + 16 * mi + gq;
                if (r0 < nN) {
                    gX[r0 * W + col] = D[mi][nt][0];
                    gX[r0 * W + col + 1] = D[mi][nt][1];
                }
                if (r0 + 8 < nN) {
                    gX[(r0 + 8) * W + col] = D[mi][nt][2];
                    gX[(r0 + 8) * W + col + 1] = D[mi][nt][3];
                }
            }
        }
    }
}

// ---------------- recurrent: cp.async double-buffered Whh, single Xs, t=0 skip ----------------
template <int DIN, int DOUT, bool RELU>
__global__ __launch_bounds__(384, 1)
void rec_k(const float* __restrict__ gX, const int* __restrict__ nidx,
           const float* __restrict__ Wp, const float* __restrict__ Wneigh,
           float* __restrict__ fout, int nN)
{
    constexpr int TM = 144, NT = 384, K4 = DIN / 4, SXA = DIN + 4;
    constexpr int W = 4 * DIN + DOUT, NCHG = (4 * DIN) / 128;
    extern __shared__ float sm[];
    float* Xs = sm;                              // TM x SXA : h (tf32)
    float* Wb[2] = { sm + TM * SXA, sm + TM * SXA + 128 * SXA };

    const int tid = threadIdx.x, lane = tid & 31, w = tid >> 5;
    const int gq = lane >> 2, tq = lane & 3, mg = w % 3, ng = w / 3, MB = 48 * mg;
    const int node0 = blockIdx.x * TM;
    const u32 WbU[2] = { smem_u32(Wb[0]), smem_u32(Wb[1]) };
    const float4* Wn4 = (const float4*)Wneigh;

    float c_loc[NCHG * 12], h_loc[NCHG * 12];
#pragma unroll
    for (int i = 0; i < NCHG * 12; i++) c_loc[i] = 0.f;

    // prefetch chunk 0 into buf 0
    {
        const float* src = Wp;
        for (int e = tid; e < 128 * K4; e += NT) {
            int row = e / K4, c4 = e % K4;
            cpa16(WbU[0] + (u32)(row * SXA + c4 * 4) * 4u, src + row * DIN + c4 * 4);
        }
        cpa_commit();
    }

    for (int t = 0; t < KNB; t++) {
        int srcs[6];
#pragma unroll
        for (int mi = 0; mi < 3; mi++)
#pragma unroll
            for (int r2 = 0; r2 < 2; r2++) {
                int nd = node0 + MB + 16 * mi + gq + 8 * r2;
                if (nd >= nN) nd = nN - 1;
                srcs[mi * 2 + r2] = nidx[nd * KNB + t];
            }
        const float* pA0 = Xs + (MB + gq) * SXA + tq;

#pragma unroll 1
        for (int ci = 0; ci < NCHG; ci++) {
            if (t > 0) {
                cpa_wait0();        // chunk ci data landed (one group outstanding)
                __syncthreads();    // everyone's copies done + prev k-loop readers done
                // prefetch chunk (ci+1)%NCHG into the freed buffer
                int cn = (ci + 1 < NCHG) ? ci + 1 : 0;
                const float* src = Wp + cn * 128 * DIN;
                u32 dstU = WbU[(ci + 1) & 1];
                for (int e = tid; e < 128 * K4; e += NT) {
                    int row = e / K4, c4 = e % K4;
                    cpa16(dstU + (u32)(row * SXA + c4 * 4) * 4u, src + row * DIN + c4 * 4);
                }
                cpa_commit();
            }
            // D init = gathered x-gates (direct LDG)
            float D[3][4][4];
#pragma unroll
            for (int mi = 0; mi < 3; mi++)
#pragma unroll
                for (int r2 = 0; r2 < 2; r2++) {
                    const float2* g2 = (const float2*)(gX +
                        (size_t)srcs[mi * 2 + r2] * W + ci * 128 + 32 * ng + 2 * tq);
#pragma unroll
                    for (int nt = 0; nt < 4; nt++) {
                        float2 v = g2[4 * nt];
                        D[mi][nt][2 * r2] = v.x;
                        D[mi][nt][2 * r2 + 1] = v.y;
                    }
                }
            if (t > 0) {
                const float* Wc = Wb[ci & 1];
#pragma unroll 4
                for (int k0 = 0; k0 < DIN; k0 += 8) {
                    u32 a[3][4], b[4][2];
#pragma unroll
                    for (int mi = 0; mi < 3; mi++) {
                        const float* pa = pA0 + 16 * mi * SXA + k0;
                        a[mi][0] = __float_as_uint(pa[0]);
                        a[mi][1] = __float_as_uint(pa[8 * SXA]);
                        a[mi][2] = __float_as_uint(pa[4]);
                        a[mi][3] = __float_as_uint(pa[8 * SXA + 4]);
                    }
#pragma unroll
                    for (int nt = 0; nt < 4; nt++) {
                        const float* pb = Wc + (32 * ng + 8 * nt + gq) * SXA + tq + k0;
                        b[nt][0] = __float_as_uint(pb[0]);
                        b[nt][1] = __float_as_uint(pb[4]);
#pragma unroll
                        for (int mi = 0; mi < 3; mi++) mma8(D[mi][nt], a[mi], b[nt]);
                    }
                }
            }
            // epilogue: LSTM cell update; h deferred to h_loc
#pragma unroll
            for (int mi = 0; mi < 3; mi++)
#pragma unroll
                for (int up = 0; up < 2; up++)
#pragma unroll
                    for (int r2 = 0; r2 < 2; r2++) {
                        float gi = D[mi][2 * up][2 * r2];
                        float gf = D[mi][2 * up][2 * r2 + 1];
                        float gg = D[mi][2 * up + 1][2 * r2];
                        float go = D[mi][2 * up + 1][2 * r2 + 1];
                        int s = ci * 12 + (mi * 2 + up) * 2 + r2;
                        float cc = siga(gf) * c_loc[s] + siga(gi) * tanha(gg);
                        c_loc[s] = cc;
                        h_loc[s] = __uint_as_float(tf32r(siga(go) * tanha(cc)));
                    }
        }
        __syncthreads();   // all Xs readers of this t done
        // write h(t)
#pragma unroll 1
        for (int ci = 0; ci < NCHG; ci++)
#pragma unroll
            for (int mi = 0; mi < 3; mi++)
#pragma unroll
                for (int up = 0; up < 2; up++)
#pragma unroll
                    for (int r2 = 0; r2 < 2; r2++)
                        Xs[(MB + 16 * mi + gq + 8 * r2) * SXA +
                           ci * 32 + 8 * ng + 4 * up + tq] =
                            h_loc[ci * 12 + (mi * 2 + up) * 2 + r2];
    }

    // ---- FC: out = selfX (precomputed, bias folded) + h_final @ Wneigh^T ----
    constexpr int NTW = DOUT / 32, CG = DOUT / 4;
    cpa_wait0();
    __syncthreads();   // h writes visible; stray prefetch done before buf0 reuse
    float* Ws = Wb[0];
    for (int e = tid; e < DOUT * K4; e += NT) {
        int r = e / K4, c4 = e % K4;
        ((uint4*)(Ws + r * SXA))[c4] = tf32x4(Wn4[r * K4 + c4]);
    }
    __syncthreads();
    const float* pAf = Xs + (MB + gq) * SXA + tq;
    float2 sxv[3][4][2];
#pragma unroll
    for (int mi = 0; mi < 3; mi++)
#pragma unroll
        for (int r2 = 0; r2 < 2; r2++) {
            int nd = node0 + MB + 16 * mi + gq + 8 * r2;
            if (nd >= nN) nd = nN - 1;
            const float2* g2 = (const float2*)(gX +
                (size_t)nd * W + 4 * DIN + CG * ng + 2 * tq);
            for (int nt = 0; nt < NTW; nt++) sxv[mi][nt][r2] = g2[4 * nt];
        }
    float D[3][4][4];
#pragma unroll
    for (int mi = 0; mi < 3; mi++)
        for (int nt = 0; nt < NTW; nt++)
#pragma unroll
            for (int j = 0; j < 4; j++) D[mi][nt][j] = 0.f;
#pragma unroll 4
    for (int k0 = 0; k0 < DIN; k0 += 8) {
        u32 a[3][4], b[4][2];
#pragma unroll
        for (int mi = 0; mi < 3; mi++) {
            const float* pa = pAf + 16 * mi * SXA + k0;
            a[mi][0] = __float_as_uint(pa[0]);
            a[mi][1] = __float_as_uint(pa[8 * SXA]);
            a[mi][2] = __float_as_uint(pa[4]);
            a[mi][3] = __float_as_uint(pa[8 * SXA + 4]);
        }
        for (int nt = 0; nt < NTW; nt++) {
            const float* pb = Ws + (CG * ng + 8 * nt + gq) * SXA + tq + k0;
            b[nt][0] = __float_as_uint(pb[0]);
            b[nt][1] = __float_as_uint(pb[4]);
#pragma unroll
            for (int mi = 0; mi < 3; mi++) mma8(D[mi][nt], a[mi], b[nt]);
        }
    }
    for (int nt = 0; nt < NTW; nt++) {
        int col = CG * ng + 8 * nt + 2 * tq;
#pragma unroll
        for (int mi = 0; mi < 3; mi++) {
            int r0 = node0 + MB + 16 * mi + gq;
            if (r0 < nN) {
                float v0 = D[mi][nt][0] + sxv[mi][nt][0].x;
                float v1 = D[mi][nt][1] + sxv[mi][nt][0].y;
                if (RELU) { v0 = fmaxf(v0, 0.f); v1 = fmaxf(v1, 0.f); }
                fout[r0 * DOUT + col] = v0; fout[r0 * DOUT + col + 1] = v1;
            }
            if (r0 + 8 < nN) {
                float v2 = D[mi][nt][2] + sxv[mi][nt][1].x;
                float v3 = D[mi][nt][3] + sxv[mi][nt][1].y;
                if (RELU) { v2 = fmaxf(v2, 0.f); v3 = fmaxf(v3, 0.f); }
                fout[(r0 + 8) * DOUT + col] = v2; fout[(r0 + 8) * DOUT + col + 1] = v3;
            }
        }
    }
}

extern "C" void kernel_launch(void* const* d_in, const int* in_sizes, int n_in,
                              void* d_out, int out_size) {
    const float* p  = (const float*)d_in[0];
    const int* nidx = (const int*)d_in[1];
    int nN = in_sizes[1] / KNB;

    float *fA, *fB, *gX, *Wp;
    cudaGetSymbolAddress((void**)&fA, g_fA);
    cudaGetSymbolAddress((void**)&fB, g_fB);
    cudaGetSymbolAddress((void**)&gX, g_gX);
    cudaGetSymbolAddress((void**)&Wp, g_Wp);

    auto smPre = [](int DIN, int DOUT) {
        return (144 * (DIN + 4) + 128 * (DIN + 4) + 4 * DIN + DOUT) * 4;
    };
    auto smRec = [](int DIN) {
        return (144 * (DIN + 4) + 2 * 128 * (DIN + 4)) * 4;
    };
    cudaFuncSetAttribute(pre_k<64, 128>,  cudaFuncAttributeMaxDynamicSharedMemorySize, smPre(64, 128));
    cudaFuncSetAttribute(pre_k<128, 128>, cudaFuncAttributeMaxDynamicSharedMemorySize, smPre(128, 128));
    cudaFuncSetAttribute(pre_k<128, 32>,  cudaFuncAttributeMaxDynamicSharedMemorySize, smPre(128, 32));
    cudaFuncSetAttribute(rec_k<64, 128, true>,  cudaFuncAttributeMaxDynamicSharedMemorySize, smRec(64));
    cudaFuncSetAttribute(rec_k<128, 128, true>, cudaFuncAttributeMaxDynamicSharedMemorySize, smRec(128));
    cudaFuncSetAttribute(rec_k<128, 32, false>, cudaFuncAttributeMaxDynamicSharedMemorySize, smRec(128));

    build_feat0<<<(nN * 64 + 255) / 256, 256>>>(p, fA, nN);

    int grid = (nN + 143) / 144;
    // layer 0
    pre_k<64, 128><<<grid, 384, smPre(64, 128)>>>(
        fA, (const float*)d_in[2], (const float*)d_in[4], (const float*)d_in[5],
        (const float*)d_in[6], (const float*)d_in[8], gX, nN);
    pack_k<<<(4 * 64 * 16 + 255) / 256, 256>>>((const float*)d_in[3], Wp, 64);
    rec_k<64, 128, true><<<grid, 384, smRec(64)>>>(
        gX, nidx, Wp, (const float*)d_in[7], fB, nN);
    // layer 1
    pre_k<128, 128><<<grid, 384, smPre(128, 128)>>>(
        fB, (const float*)d_in[9], (const float*)d_in[11], (const float*)d_in[12],
        (const float*)d_in[13], (const float*)d_in[15], gX, nN);
    pack_k<<<(4 * 128 * 32 + 255) / 256, 256>>>((const float*)d_in[10], Wp, 128);
    rec_k<128, 128, true><<<grid, 384, smRec(128)>>>(
        gX, nidx, Wp, (const float*)d_in[14], fA, nN);
    // layer 2
    pre_k<128, 32><<<grid, 384, smPre(128, 32)>>>(
        fA, (const float*)d_in[16], (const float*)d_in[18], (const float*)d_in[19],
        (const float*)d_in[20], (const float*)d_in[22], gX, nN);
    pack_k<<<(4 * 128 * 32 + 255) / 256, 256>>>((const float*)d_in[17], Wp, 128);
    rec_k<128, 32, false><<<grid, 384, smRec(128)>>>(
        gX, nidx, Wp, (const float*)d_in[21], (float*)d_out, nN);
}

// round 13
// speedup vs baseline: 1.0242x; 1.0242x over previous
#include <cuda_runtime.h>
#define KNB 16
typedef unsigned u32;

__device__ __align__(256) float g_fA[20096 * 128];
__device__ __align__(256) float g_fB[20096 * 128];
__device__ __align__(256) float g_gX[20096 * 640];
__device__ __align__(256) float g_Wp[512 * 128];

__device__ __forceinline__ float tanha(float x) {
    float r; asm("tanh.approx.f32 %0, %1;" : "=f"(r) : "f"(x)); return r;
}
__device__ __forceinline__ float siga(float x) {
    return fmaf(tanha(0.5f * x), 0.5f, 0.5f);
}
__device__ __forceinline__ u32 tf32r(float f) {
    u32 r; asm("cvt.rna.tf32.f32 %0, %1;" : "=r"(r) : "f"(f)); return r;
}
__device__ __forceinline__ uint4 tf32x4(float4 v) {
    return make_uint4(tf32r(v.x), tf32r(v.y), tf32r(v.z), tf32r(v.w));
}
__device__ __forceinline__ void mma8(float* d, const u32* a, const u32* b) {
    asm volatile("mma.sync.aligned.m16n8k8.row.col.f32.tf32.tf32.f32 "
        "{%0,%1,%2,%3},{%4,%5,%6,%7},{%8,%9},{%0,%1,%2,%3};"
        : "+f"(d[0]), "+f"(d[1]), "+f"(d[2]), "+f"(d[3])
        : "r"(a[0]), "r"(a[1]), "r"(a[2]), "r"(a[3]), "r"(b[0]), "r"(b[1]));
}
__device__ __forceinline__ u32 smem_u32(const void* p) {
    u32 a; asm("{ .reg .u64 t; cvta.to.shared.u64 t, %1; cvt.u32.u64 %0, t; }" : "=r"(a) : "l"(p)); return a;
}
__device__ __forceinline__ void cpa16(u32 dst, const void* src) {
    asm volatile("cp.async.cg.shared.global [%0], [%1], 16;" :: "r"(dst), "l"(src));
}
__device__ __forceinline__ void cpa_commit() { asm volatile("cp.async.commit_group;"); }
__device__ __forceinline__ void cpa_wait0()  { asm volatile("cp.async.wait_group 0;" ::: "memory"); }

// Gate-column permutation (see R10): thread (gq,tq) of warp ng owns all 4 gates
// of its units directly in its MMA output registers.
__device__ __forceinline__ int gmap(int c, int DIN) {
    int blk = c >> 5, w5 = c & 31;
    int nt = w5 >> 3, tq = (w5 >> 1) & 3, e = w5 & 1;
    return (2 * (nt & 1) + e) * DIN + blk * 8 + (nt >> 1) * 4 + tq;
}

__global__ void build_feat0(const float* __restrict__ p, float* __restrict__ f0, int nN) {
    int i = blockIdx.x * blockDim.x + threadIdx.x;
    if (i >= nN * 64) return;
    int node = i >> 6, k = i & 63;
    f0[i] = (k == 0) ? (16.0f / (float)nN) : p[node * 63 + (k - 1)];
}

// pre-pack Whh: tf32-rounded, gmap-permuted rows, contiguous DIN-float rows
__global__ void pack_k(const float* __restrict__ Whh, float* __restrict__ Wp, int DIN) {
    int K4 = DIN >> 2;
    int e = blockIdx.x * 256 + threadIdx.x;
    if (e >= 4 * DIN * K4) return;
    int row = e / K4, c4 = e % K4;
    ((uint4*)Wp)[e] = tf32x4(((const float4*)Whh)[gmap(row, DIN) * K4 + c4]);
}

// ---------------- precompute: gX[n] = feat[n] @ [Wih(permuted) | Wself]^T + bias ----------------
// Gate cols stored in gather-friendly layout: float idx = ng*(NCHG*32) + ci*32 + tq*8 + nt*2 + e
// so a rec thread's per-chunk x-gates are one contiguous 32B run (tq lanes fill a 128B line).
template <int DIN, int DOUT>
__global__ __launch_bounds__(384, 1)
void pre_k(const float* __restrict__ feat,
           const float* __restrict__ Wih, const float* __restrict__ bih,
           const float* __restrict__ bhh, const float* __restrict__ Wself,
           const float* __restrict__ bo, float* __restrict__ gX, int nN)
{
    constexpr int TM = 144, NT = 384, K4 = DIN / 4, SXA = DIN + 4, W = 4 * DIN + DOUT;
    constexpr int NCHG = (4 * DIN) / 128;
    extern __shared__ float sm[];
    float* Xs = sm;
    float* Ws = sm + TM * SXA;
    float* CB = Ws + 128 * SXA;

    const int tid = threadIdx.x, lane = tid & 31, w = tid >> 5;
    const int gq = lane >> 2, tq = lane & 3, mg = w % 3, ng = w / 3, MB = 48 * mg;
    const int node0 = blockIdx.x * TM;
    const float4* fin4 = (const float4*)feat;
    const float4* Wi4 = (const float4*)Wih;
    const float4* Wsf4 = (const float4*)Wself;

    for (int e = tid; e < 4 * DIN; e += NT) {
        int sr = gmap(e, DIN);
        CB[e] = bih[sr] + bhh[sr];
    }
    for (int e = tid; e < DOUT; e += NT) CB[4 * DIN + e] = bo[e];
    for (int e = tid; e < TM * K4; e += NT) {
        int row = e / K4, c4 = e % K4;
        int nd = node0 + row; if (nd >= nN) nd = nN - 1;
        ((uint4*)(Xs + row * SXA))[c4] = tf32x4(fin4[nd * K4 + c4]);
    }
    const float* pA0 = Xs + (MB + gq) * SXA + tq;

    for (int c0 = 0; c0 < W; c0 += 128) {
        const int CR = (W - c0 < 128) ? (W - c0) : 128;
        const int NTW = CR / 32, CG = CR / 4;
        __syncthreads();
        for (int e = tid; e < CR * K4; e += NT) {
            int r = e / K4, c4 = e % K4;
            int gc = c0 + r;
            float4 v = (gc < 4 * DIN) ? Wi4[gmap(gc, DIN) * K4 + c4]
                                      : Wsf4[(gc - 4 * DIN) * K4 + c4];
            ((uint4*)(Ws + r * SXA))[c4] = tf32x4(v);
        }
        __syncthreads();
        float D[3][4][4];
        for (int nt = 0; nt < NTW; nt++) {
            float b0 = CB[c0 + CG * ng + 8 * nt + 2 * tq];
            float b1 = CB[c0 + CG * ng + 8 * nt + 2 * tq + 1];
#pragma unroll
            for (int mi = 0; mi < 3; mi++) {
                D[mi][nt][0] = b0; D[mi][nt][1] = b1;
                D[mi][nt][2] = b0; D[mi][nt][3] = b1;
            }
        }
#pragma unroll 4
        for (int k0 = 0; k0 < DIN; k0 += 8) {
            u32 a[3][4], b[4][2];
#pragma unroll
            for (int mi = 0; mi < 3; mi++) {
                const float* pa = pA0 + 16 * mi * SXA + k0;
                a[mi][0] = __float_as_uint(pa[0]);
                a[mi][1] = __float_as_uint(pa[8 * SXA]);
                a[mi][2] = __float_as_uint(pa[4]);
                a[mi][3] = __float_as_uint(pa[8 * SXA + 4]);
            }
            for (int nt = 0; nt < NTW; nt++) {
                const float* pb = Ws + (CG * ng + 8 * nt + gq) * SXA + tq + k0;
                b[nt][0] = __float_as_uint(pb[0]);
                b[nt][1] = __float_as_uint(pb[4]);
#pragma unroll
                for (int mi = 0; mi < 3; mi++) mma8(D[mi][nt], a[mi], b[nt]);
            }
        }
        bool isGate = (c0 < 4 * DIN);
        int ci = c0 >> 7;
        for (int nt = 0; nt < NTW; nt++) {
            int col = isGate ? (ng * (NCHG * 32) + ci * 32 + tq * 8 + nt * 2)
                             : (c0 + CG * ng + 8 * nt + 2 * tq);
#pragma unroll
            for (int mi = 0; mi < 3; mi++) {
                int r0 = node0 + MB + 16 * mi + gq;
                if (r0 < nN) {
                    gX[r0 * W + col] = D[mi][nt][0];
                    gX[r0 * W + col + 1] = D[mi][nt][1];
                }
                if (r0 + 8 < nN) {
                    gX[(r0 + 8) * W + col] = D[mi][nt][2];
                    gX[(r0 + 8) * W + col + 1] = D[mi][nt][3];
                }
            }
        }
    }
}

// ---------------- recurrent ----------------
// NCHG==2 (DIN=64): both Whh chunks resident in SMEM, 2 barriers/t.
// NCHG==4 (DIN=128): cp.async double-buffered chunk pipeline.
template <int DIN, int DOUT, bool RELU>
__global__ __launch_bounds__(384, 1)
void rec_k(const float* __restrict__ gX, const int* __restrict__ nidx,
           const float* __restrict__ Wp, const float* __restrict__ Wneigh,
           float* __restrict__ fout, int nN)
{
    constexpr int TM = 144, NT = 384, K4 = DIN / 4, SXA = DIN + 4;
    constexpr int W = 4 * DIN + DOUT, NCHG = (4 * DIN) / 128;
    extern __shared__ float sm[];
    float* Xs = sm;                              // TM x SXA : h (tf32)
    float* Wb[2] = { sm + TM * SXA, sm + TM * SXA + 128 * SXA };

    const int tid = threadIdx.x, lane = tid & 31, w = tid >> 5;
    const int gq = lane >> 2, tq = lane & 3, mg = w % 3, ng = w / 3, MB = 48 * mg;
    const int node0 = blockIdx.x * TM;
    const u32 WbU[2] = { smem_u32(Wb[0]), smem_u32(Wb[1]) };
    const float4* Wn4 = (const float4*)Wneigh;

    float c_loc[NCHG * 12], h_loc[NCHG * 12];
#pragma unroll
    for (int i = 0; i < NCHG * 12; i++) c_loc[i] = 0.f;

    // prologue staging
    if (NCHG <= 2) {
        // both chunks resident
        for (int c = 0; c < NCHG; c++) {
            const float* src = Wp + c * 128 * DIN;
            for (int e = tid; e < 128 * K4; e += NT) {
                int row = e / K4, c4 = e % K4;
                cpa16(WbU[c] + (u32)(row * SXA + c4 * 4) * 4u, src + row * DIN + c4 * 4);
            }
        }
        cpa_commit();
        cpa_wait0();
        __syncthreads();
    } else {
        const float* src = Wp;
        for (int e = tid; e < 128 * K4; e += NT) {
            int row = e / K4, c4 = e % K4;
            cpa16(WbU[0] + (u32)(row * SXA + c4 * 4) * 4u, src + row * DIN + c4 * 4);
        }
        cpa_commit();
    }

    for (int t = 0; t < KNB; t++) {
        int srcs[6];
#pragma unroll
        for (int mi = 0; mi < 3; mi++)
#pragma unroll
            for (int r2 = 0; r2 < 2; r2++) {
                int nd = node0 + MB + 16 * mi + gq + 8 * r2;
                if (nd >= nN) nd = nN - 1;
                srcs[mi * 2 + r2] = nidx[nd * KNB + t];
            }
        const float* pA0 = Xs + (MB + gq) * SXA + tq;

#pragma unroll 1
        for (int ci = 0; ci < NCHG; ci++) {
            if (NCHG > 2 && t > 0) {
                cpa_wait0();
                __syncthreads();
                int cn = (ci + 1 < NCHG) ? ci + 1 : 0;
                const float* src = Wp + cn * 128 * DIN;
                u32 dstU = WbU[(ci + 1) & 1];
                for (int e = tid; e < 128 * K4; e += NT) {
                    int row = e / K4, c4 = e % K4;
                    cpa16(dstU + (u32)(row * SXA + c4 * 4) * 4u, src + row * DIN + c4 * 4);
                }
                cpa_commit();
            }
            // x-gates: contiguous 32B per row-chunk (permuted layout), 2x LDG.128
            float4 ga[6], gb[6];
#pragma unroll
            for (int i = 0; i < 6; i++) {
                const float4* g4 = (const float4*)(gX +
                    (size_t)srcs[i] * W + (size_t)(ng * NCHG + ci) * 32 + tq * 8);
                ga[i] = g4[0];
                gb[i] = g4[1];
            }
            float D[3][4][4];
#pragma unroll
            for (int mi = 0; mi < 3; mi++)
#pragma unroll
                for (int nt = 0; nt < 4; nt++)
#pragma unroll
                    for (int j = 0; j < 4; j++) D[mi][nt][j] = 0.f;
            if (t > 0) {
                const float* Wc = Wb[(NCHG > 2) ? (ci & 1) : ci];
#pragma unroll 4
                for (int k0 = 0; k0 < DIN; k0 += 8) {
                    u32 a[3][4], b[4][2];
#pragma unroll
                    for (int mi = 0; mi < 3; mi++) {
                        const float* pa = pA0 + 16 * mi * SXA + k0;
                        a[mi][0] = __float_as_uint(pa[0]);
                        a[mi][1] = __float_as_uint(pa[8 * SXA]);
                        a[mi][2] = __float_as_uint(pa[4]);
                        a[mi][3] = __float_as_uint(pa[8 * SXA + 4]);
                    }
#pragma unroll
                    for (int nt = 0; nt < 4; nt++) {
                        const float* pb = Wc + (32 * ng + 8 * nt + gq) * SXA + tq + k0;
                        b[nt][0] = __float_as_uint(pb[0]);
                        b[nt][1] = __float_as_uint(pb[4]);
#pragma unroll
                        for (int mi = 0; mi < 3; mi++) mma8(D[mi][nt], a[mi], b[nt]);
                    }
                }
            }
            // epilogue: add x-gates (nt pairs packed in ga/gb), LSTM cell update
#pragma unroll
            for (int mi = 0; mi < 3; mi++)
#pragma unroll
                for (int up = 0; up < 2; up++)
#pragma unroll
                    for (int r2 = 0; r2 < 2; r2++) {
                        int i = mi * 2 + r2;
                        float xa0 = up ? gb[i].x : ga[i].x;
                        float xa1 = up ? gb[i].y : ga[i].y;
                        float xb0 = up ? gb[i].z : ga[i].z;
                        float xb1 = up ? gb[i].w : ga[i].w;
                        float gi = D[mi][2 * up][2 * r2]     + xa0;
                        float gf = D[mi][2 * up][2 * r2 + 1] + xa1;
                        float gg = D[mi][2 * up + 1][2 * r2]     + xb0;
                        float go = D[mi][2 * up + 1][2 * r2 + 1] + xb1;
                        int s = ci * 12 + (mi * 2 + up) * 2 + r2;
                        float cc = siga(gf) * c_loc[s] + siga(gi) * tanha(gg);
                        c_loc[s] = cc;
                        h_loc[s] = __uint_as_float(tf32r(siga(go) * tanha(cc)));
                    }
        }
        __syncthreads();   // all Xs readers of this t done
        // write h(t)
#pragma unroll 1
        for (int ci = 0; ci < NCHG; ci++)
#pragma unroll
            for (int mi = 0; mi < 3; mi++)
#pragma unroll
                for (int up = 0; up < 2; up++)
#pragma unroll
                    for (int r2 = 0; r2 < 2; r2++)
                        Xs[(MB + 16 * mi + gq + 8 * r2) * SXA +
                           ci * 32 + 8 * ng + 4 * up + tq] =
                            h_loc[ci * 12 + (mi * 2 + up) * 2 + r2];
        if (NCHG <= 2) __syncthreads();   // h visible for next t (no per-chunk sync)
    }

    // ---- FC: out = selfX (precomputed, bias folded) + h_final @ Wneigh^T ----
    constexpr int NTW = DOUT / 32, CG = DOUT / 4;
    cpa_wait0();
    __syncthreads();   // h writes visible; stray prefetch done before buf0 reuse
    float* Ws = Wb[0];
    for (int e = tid; e < DOUT * K4; e += NT) {
        int r = e / K4, c4 = e % K4;
        ((uint4*)(Ws + r * SXA))[c4] = tf32x4(Wn4[r * K4 + c4]);
    }
    __syncthreads();
    const float* pAf = Xs + (MB + gq) * SXA + tq;
    float2 sxv[3][4][2];
#pragma unroll
    for (int mi = 0; mi < 3; mi++)
#pragma unroll
        for (int r2 = 0; r2 < 2; r2++) {
            int nd = node0 + MB + 16 * mi + gq + 8 * r2;
            if (nd >= nN) nd = nN - 1;
            const float2* g2 = (const float2*)(gX +
                (size_t)nd * W + 4 * DIN + CG * ng + 2 * tq);
            for (int nt = 0; nt < NTW; nt++) sxv[mi][nt][r2] = g2[4 * nt];
        }
    float D[3][4][4];
#pragma unroll
    for (int mi = 0; mi < 3; mi++)
        for (int nt = 0; nt < NTW; nt++)
#pragma unroll
            for (int j = 0; j < 4; j++) D[mi][nt][j] = 0.f;
#pragma unroll 4
    for (int k0 = 0; k0 < DIN; k0 += 8) {
        u32 a[3][4], b[4][2];
#pragma unroll
        for (int mi = 0; mi < 3; mi++) {
            const float* pa = pAf + 16 * mi * SXA + k0;
            a[mi][0] = __float_as_uint(pa[0]);
            a[mi][1] = __float_as_uint(pa[8 * SXA]);
            a[mi][2] = __float_as_uint(pa[4]);
            a[mi][3] = __float_as_uint(pa[8 * SXA + 4]);
        }
        for (int nt = 0; nt < NTW; nt++) {
            const float* pb = Ws + (CG * ng + 8 * nt + gq) * SXA + tq + k0;
            b[nt][0] = __float_as_uint(pb[0]);
            b[nt][1] = __float_as_uint(pb[4]);
#pragma unroll
            for (int mi = 0; mi < 3; mi++) mma8(D[mi][nt], a[mi], b[nt]);
        }
    }
    for (int nt = 0; nt < NTW; nt++) {
        int col = CG * ng + 8 * nt + 2 * tq;
#pragma unroll
        for (int mi = 0; mi < 3; mi++) {
            int r0 = node0 + MB + 16 * mi + gq;
            if (r0 < nN) {
                float v0 = D[mi][nt][0] + sxv[mi][nt][0].x;
                float v1 = D[mi][nt][1] + sxv[mi][nt][0].y;
                if (RELU) { v0 = fmaxf(v0, 0.f); v1 = fmaxf(v1, 0.f); }
                fout[r0 * DOUT + col] = v0; fout[r0 * DOUT + col + 1] = v1;
            }
            if (r0 + 8 < nN) {
                float v2 = D[mi][nt][2] + sxv[mi][nt][1].x;
                float v3 = D[mi][nt][3] + sxv[mi][nt][1].y;
                if (RELU) { v2 = fmaxf(v2, 0.f); v3 = fmaxf(v3, 0.f); }
                fout[(r0 + 8) * DOUT + col] = v2; fout[(r0 + 8) * DOUT + col + 1] = v3;
            }
        }
    }
}

extern "C" void kernel_launch(void* const* d_in, const int* in_sizes, int n_in,
                              void* d_out, int out_size) {
    const float* p  = (const float*)d_in[0];
    const int* nidx = (const int*)d_in[1];
    int nN = in_sizes[1] / KNB;

    float *fA, *fB, *gX, *Wp;
    cudaGetSymbolAddress((void**)&fA, g_fA);
    cudaGetSymbolAddress((void**)&fB, g_fB);
    cudaGetSymbolAddress((void**)&gX, g_gX);
    cudaGetSymbolAddress((void**)&Wp, g_Wp);

    auto smPre = [](int DIN, int DOUT) {
        return (144 * (DIN + 4) + 128 * (DIN + 4) + 4 * DIN + DOUT) * 4;
    };
    auto smRec = [](int DIN) {
        return (144 * (DIN + 4) + 2 * 128 * (DIN + 4)) * 4;
    };
    cudaFuncSetAttribute(pre_k<64, 128>,  cudaFuncAttributeMaxDynamicSharedMemorySize, smPre(64, 128));
    cudaFuncSetAttribute(pre_k<128, 128>, cudaFuncAttributeMaxDynamicSharedMemorySize, smPre(128, 128));
    cudaFuncSetAttribute(pre_k<128, 32>,  cudaFuncAttributeMaxDynamicSharedMemorySize, smPre(128, 32));
    cudaFuncSetAttribute(rec_k<64, 128, true>,  cudaFuncAttributeMaxDynamicSharedMemorySize, smRec(64));
    cudaFuncSetAttribute(rec_k<128, 128, true>, cudaFuncAttributeMaxDynamicSharedMemorySize, smRec(128));
    cudaFuncSetAttribute(rec_k<128, 32, false>, cudaFuncAttributeMaxDynamicSharedMemorySize, smRec(128));

    build_feat0<<<(nN * 64 + 255) / 256, 256>>>(p, fA, nN);

    int grid = (nN + 143) / 144;
    // layer 0
    pre_k<64, 128><<<grid, 384, smPre(64, 128)>>>(
        fA, (const float*)d_in[2], (const float*)d_in[4], (const float*)d_in[5],
        (const float*)d_in[6], (const float*)d_in[8], gX, nN);
    pack_k<<<(4 * 64 * 16 + 255) / 256, 256>>>((const float*)d_in[3], Wp, 64);
    rec_k<64, 128, true><<<grid, 384, smRec(64)>>>(
        gX, nidx, Wp, (const float*)d_in[7], fB, nN);
    // layer 1
    pre_k<128, 128><<<grid, 384, smPre(128, 128)>>>(
        fB, (const float*)d_in[9], (const float*)d_in[11], (const float*)d_in[12],
        (const float*)d_in[13], (const float*)d_in[15], gX, nN);
    pack_k<<<(4 * 128 * 32 + 255) / 256, 256>>>((const float*)d_in[10], Wp, 128);
    rec_k<128, 128, true><<<grid, 384, smRec(128)>>>(
        gX, nidx, Wp, (const float*)d_in[14], fA, nN);
    // layer 2
    pre_k<128, 32><<<grid, 384, smPre(128, 32)>>>(
        fA, (const float*)d_in[16], (const float*)d_in[18], (const float*)d_in[19],
        (const float*)d_in[20], (const float*)d_in[22], gX, nN);
    pack_k<<<(4 * 128 * 32 + 255) / 256, 256>>>((const float*)d_in[17], Wp, 128);
    rec_k<128, 32, false><<<grid, 384, smRec(128)>>>(
        gX, nidx, Wp, (const float*)d_in[21], (float*)d_out, nN);
}

// round 14
// speedup vs baseline: 1.0435x; 1.0188x over previous
#include <cuda_runtime.h>
#define KNB 16
typedef unsigned u32;

__device__ __align__(256) float g_fA[20096 * 128];
__device__ __align__(256) float g_fB[20096 * 128];
__device__ __align__(256) float g_gX[20096 * 640];
__device__ __align__(256) float g_Wp[512 * 128];

__device__ __forceinline__ float tanha(float x) {
    float r; asm("tanh.approx.f32 %0, %1;" : "=f"(r) : "f"(x)); return r;
}
__device__ __forceinline__ float siga(float x) {
    return fmaf(tanha(0.5f * x), 0.5f, 0.5f);
}
__device__ __forceinline__ u32 tf32r(float f) {
    u32 r; asm("cvt.rna.tf32.f32 %0, %1;" : "=r"(r) : "f"(f)); return r;
}
__device__ __forceinline__ uint4 tf32x4(float4 v) {
    return make_uint4(tf32r(v.x), tf32r(v.y), tf32r(v.z), tf32r(v.w));
}
__device__ __forceinline__ void mma8(float* d, const u32* a, const u32* b) {
    asm volatile("mma.sync.aligned.m16n8k8.row.col.f32.tf32.tf32.f32 "
        "{%0,%1,%2,%3},{%4,%5,%6,%7},{%8,%9},{%0,%1,%2,%3};"
        : "+f"(d[0]), "+f"(d[1]), "+f"(d[2]), "+f"(d[3])
        : "r"(a[0]), "r"(a[1]), "r"(a[2]), "r"(a[3]), "r"(b[0]), "r"(b[1]));
}
__device__ __forceinline__ u32 smem_u32(const void* p) {
    u32 a; asm("{ .reg .u64 t; cvta.to.shared.u64 t, %1; cvt.u32.u64 %0, t; }" : "=r"(a) : "l"(p)); return a;
}
__device__ __forceinline__ void cpa16(u32 dst, const void* src) {
    asm volatile("cp.async.cg.shared.global [%0], [%1], 16;" :: "r"(dst), "l"(src));
}
__device__ __forceinline__ void cpa_commit() { asm volatile("cp.async.commit_group;"); }
__device__ __forceinline__ void cpa_wait0()  { asm volatile("cp.async.wait_group 0;" ::: "memory"); }

// Gate-column permutation (see R10): thread (gq,tq) of warp ng owns all 4 gates
// of its units directly in its MMA output registers.
__device__ __forceinline__ int gmap(int c, int DIN) {
    int blk = c >> 5, w5 = c & 31;
    int nt = w5 >> 3, tq = (w5 >> 1) & 3, e = w5 & 1;
    return (2 * (nt & 1) + e) * DIN + blk * 8 + (nt >> 1) * 4 + tq;
}
// k-interleave within each 8-col group: [k0,k4,k1,k5,k2,k6,k3,k7]
// -> fragment pair (k, k+4) is one aligned 8-byte LDS.64.
__device__ __forceinline__ int ilk(int k) {
    return (k & ~7) + ((k & 3) << 1) + ((k >> 2) & 1);
}
// interleave 8 consecutive tf32 words (A=k0..k3, B=k4..k7) into layout order
__device__ __forceinline__ void ilsh(uint4 A, uint4 B, uint4& o0, uint4& o1) {
    o0 = make_uint4(A.x, B.x, A.y, B.y);
    o1 = make_uint4(A.z, B.z, A.w, B.w);
}
// A-fragment loader: 2x LDS.64 per m-tile
__device__ __forceinline__ void ldA(u32* a, const float* pa, int SXA) {
    float2 lo = *(const float2*)pa;
    float2 hi = *(const float2*)(pa + 8 * SXA);
    a[0] = __float_as_uint(lo.x); a[1] = __float_as_uint(hi.x);
    a[2] = __float_as_uint(lo.y); a[3] = __float_as_uint(hi.y);
}
__device__ __forceinline__ void ldB(u32* b, const float* pb) {
    float2 v = *(const float2*)pb;
    b[0] = __float_as_uint(v.x); b[1] = __float_as_uint(v.y);
}

__global__ void build_feat0(const float* __restrict__ p, float* __restrict__ f0, int nN) {
    int i = blockIdx.x * blockDim.x + threadIdx.x;
    if (i >= nN * 64) return;
    int node = i >> 6, k = i & 63;
    f0[i] = (k == 0) ? (16.0f / (float)nN) : p[node * 63 + (k - 1)];
}

// pre-pack Whh: tf32-rounded, gmap-permuted rows, ilk-interleaved cols
__global__ void pack_k(const float* __restrict__ Whh, float* __restrict__ Wp, int DIN) {
    int e = blockIdx.x * 256 + threadIdx.x;
    if (e >= 4 * DIN * DIN) return;
    int row = e / DIN, kk = e % DIN;
    Wp[row * DIN + ilk(kk)] =
        __uint_as_float(tf32r(Whh[gmap(row, DIN) * DIN + kk]));
}

// ---------------- precompute: gX[n] = feat[n] @ [Wih(permuted) | Wself]^T + bias ----------------
// gX gate cols in gather-friendly layout (see R13). SMEM tiles ilk-interleaved for LDS.64 frags.
template <int DIN, int DOUT>
__global__ __launch_bounds__(384, 1)
void pre_k(const float* __restrict__ feat,
           const float* __restrict__ Wih, const float* __restrict__ bih,
           const float* __restrict__ bhh, const float* __restrict__ Wself,
           const float* __restrict__ bo, float* __restrict__ gX, int nN)
{
    constexpr int TM = 144, NT = 384, K4 = DIN / 4, G8 = DIN / 8;
    constexpr int SXA = DIN + 8, W = 4 * DIN + DOUT;
    constexpr int NCHG = (4 * DIN) / 128;
    extern __shared__ float sm[];
    float* Xs = sm;
    float* Ws = sm + TM * SXA;
    float* CB = Ws + 128 * SXA;

    const int tid = threadIdx.x, lane = tid & 31, w = tid >> 5;
    const int gq = lane >> 2, tq = lane & 3, mg = w % 3, ng = w / 3, MB = 48 * mg;
    const int node0 = blockIdx.x * TM;
    const float4* fin4 = (const float4*)feat;
    const float4* Wi4 = (const float4*)Wih;
    const float4* Wsf4 = (const float4*)Wself;

    for (int e = tid; e < 4 * DIN; e += NT) {
        int sr = gmap(e, DIN);
        CB[e] = bih[sr] + bhh[sr];
    }
    for (int e = tid; e < DOUT; e += NT) CB[4 * DIN + e] = bo[e];
    for (int e = tid; e < TM * G8; e += NT) {
        int row = e / G8, g8 = e % G8;
        int nd = node0 + row; if (nd >= nN) nd = nN - 1;
        uint4 A = tf32x4(fin4[nd * K4 + 2 * g8]);
        uint4 B = tf32x4(fin4[nd * K4 + 2 * g8 + 1]);
        uint4 o0, o1; ilsh(A, B, o0, o1);
        ((uint4*)(Xs + row * SXA + 8 * g8))[0] = o0;
        ((uint4*)(Xs + row * SXA + 8 * g8))[1] = o1;
    }
    const float* pA0 = Xs + (MB + gq) * SXA + 2 * tq;

    for (int c0 = 0; c0 < W; c0 += 128) {
        const int CR = (W - c0 < 128) ? (W - c0) : 128;
        const int NTW = CR / 32, CG = CR / 4;
        __syncthreads();
        for (int e = tid; e < CR * G8; e += NT) {
            int r = e / G8, g8 = e % G8;
            int gc = c0 + r;
            uint4 A, B;
            if (gc < 4 * DIN) {
                int sr = gmap(gc, DIN);
                A = tf32x4(Wi4[sr * K4 + 2 * g8]);
                B = tf32x4(Wi4[sr * K4 + 2 * g8 + 1]);
            } else {
                int sr = gc - 4 * DIN;
                A = tf32x4(Wsf4[sr * K4 + 2 * g8]);
                B = tf32x4(Wsf4[sr * K4 + 2 * g8 + 1]);
            }
            uint4 o0, o1; ilsh(A, B, o0, o1);
            ((uint4*)(Ws + r * SXA + 8 * g8))[0] = o0;
            ((uint4*)(Ws + r * SXA + 8 * g8))[1] = o1;
        }
        __syncthreads();
        float D[3][4][4];
        for (int nt = 0; nt < NTW; nt++) {
            float b0 = CB[c0 + CG * ng + 8 * nt + 2 * tq];
            float b1 = CB[c0 + CG * ng + 8 * nt + 2 * tq + 1];
#pragma unroll
            for (int mi = 0; mi < 3; mi++) {
                D[mi][nt][0] = b0; D[mi][nt][1] = b1;
                D[mi][nt][2] = b0; D[mi][nt][3] = b1;
            }
        }
#pragma unroll 4
        for (int g8 = 0; g8 < G8; g8++) {
            u32 a[3][4], b[4][2];
#pragma unroll
            for (int mi = 0; mi < 3; mi++)
                ldA(a[mi], pA0 + 16 * mi * SXA + 8 * g8, SXA);
            for (int nt = 0; nt < NTW; nt++) {
                ldB(b[nt], Ws + (CG * ng + 8 * nt + gq) * SXA + 2 * tq + 8 * g8);
#pragma unroll
                for (int mi = 0; mi < 3; mi++) mma8(D[mi][nt], a[mi], b[nt]);
            }
        }
        bool isGate = (c0 < 4 * DIN);
        int ci = c0 >> 7;
        for (int nt = 0; nt < NTW; nt++) {
            int col = isGate ? (ng * (NCHG * 32) + ci * 32 + tq * 8 + nt * 2)
                             : (c0 + CG * ng + 8 * nt + 2 * tq);
#pragma unroll
            for (int mi = 0; mi < 3; mi++) {
                int r0 = node0 + MB + 16 * mi + gq;
                if (r0 < nN) {
                    gX[r0 * W + col] = D[mi][nt][0];
                    gX[r0 * W + col + 1] = D[mi][nt][1];
                }
                if (r0 + 8 < nN) {
                    gX[(r0 + 8) * W + col] = D[mi][nt][2];
                    gX[(r0 + 8) * W + col + 1] = D[mi][nt][3];
                }
            }
        }
    }
}

// ---------------- recurrent ----------------
// NCHG==2 (DIN=64): both Whh chunks resident in SMEM, 2 barriers/t.
// NCHG==4 (DIN=128): cp.async double-buffered chunk pipeline.
template <int DIN, int DOUT, bool RELU>
__global__ __launch_bounds__(384, 1)
void rec_k(const float* __restrict__ gX, const int* __restrict__ nidx,
           const float* __restrict__ Wp, const float* __restrict__ Wneigh,
           float* __restrict__ fout, int nN)
{
    constexpr int TM = 144, NT = 384, K4 = DIN / 4, G8 = DIN / 8, SXA = DIN + 8;
    constexpr int W = 4 * DIN + DOUT, NCHG = (4 * DIN) / 128;
    extern __shared__ float sm[];
    float* Xs = sm;                              // TM x SXA : h (tf32, ilk layout)
    float* Wb[2] = { sm + TM * SXA, sm + TM * SXA + 128 * SXA };

    const int tid = threadIdx.x, lane = tid & 31, w = tid >> 5;
    const int gq = lane >> 2, tq = lane & 3, mg = w % 3, ng = w / 3, MB = 48 * mg;
    const int node0 = blockIdx.x * TM;
    const u32 WbU[2] = { smem_u32(Wb[0]), smem_u32(Wb[1]) };
    const float4* Wn4 = (const float4*)Wneigh;

    float c_loc[NCHG * 12], h_loc[NCHG * 12];
#pragma unroll
    for (int i = 0; i < NCHG * 12; i++) c_loc[i] = 0.f;

    // prologue staging (Wp already tf32 + permuted + ilk-interleaved: raw copy)
    if (NCHG <= 2) {
        for (int c = 0; c < NCHG; c++) {
            const float* src = Wp + c * 128 * DIN;
            for (int e = tid; e < 128 * K4; e += NT) {
                int row = e / K4, c4 = e % K4;
                cpa16(WbU[c] + (u32)(row * SXA + c4 * 4) * 4u, src + row * DIN + c4 * 4);
            }
        }
        cpa_commit();
        cpa_wait0();
        __syncthreads();
    } else {
        const float* src = Wp;
        for (int e = tid; e < 128 * K4; e += NT) {
            int row = e / K4, c4 = e % K4;
            cpa16(WbU[0] + (u32)(row * SXA + c4 * 4) * 4u, src + row * DIN + c4 * 4);
        }
        cpa_commit();
    }

    for (int t = 0; t < KNB; t++) {
        int srcs[6];
#pragma unroll
        for (int mi = 0; mi < 3; mi++)
#pragma unroll
            for (int r2 = 0; r2 < 2; r2++) {
                int nd = node0 + MB + 16 * mi + gq + 8 * r2;
                if (nd >= nN) nd = nN - 1;
                srcs[mi * 2 + r2] = nidx[nd * KNB + t];
            }
        const float* pA0 = Xs + (MB + gq) * SXA + 2 * tq;

#pragma unroll 1
        for (int ci = 0; ci < NCHG; ci++) {
            // x-gates: issued BEFORE the barrier so LDG latency hides under the drain
            float4 ga[6], gb[6];
#pragma unroll
            for (int i = 0; i < 6; i++) {
                const float4* g4 = (const float4*)(gX +
                    (size_t)srcs[i] * W + (size_t)(ng * NCHG + ci) * 32 + tq * 8);
                ga[i] = g4[0];
                gb[i] = g4[1];
            }
            if (NCHG > 2 && t > 0) {
                cpa_wait0();
                __syncthreads();
                int cn = (ci + 1 < NCHG) ? ci + 1 : 0;
                const float* src = Wp + cn * 128 * DIN;
                u32 dstU = WbU[(ci + 1) & 1];
                for (int e = tid; e < 128 * K4; e += NT) {
                    int row = e / K4, c4 = e % K4;
                    cpa16(dstU + (u32)(row * SXA + c4 * 4) * 4u, src + row * DIN + c4 * 4);
                }
                cpa_commit();
            }
            float D[3][4][4];
#pragma unroll
            for (int mi = 0; mi < 3; mi++)
#pragma unroll
                for (int nt = 0; nt < 4; nt++)
#pragma unroll
                    for (int j = 0; j < 4; j++) D[mi][nt][j] = 0.f;
            if (t > 0) {
                const float* Wc = Wb[(NCHG > 2) ? (ci & 1) : ci];
#pragma unroll 4
                for (int g8 = 0; g8 < G8; g8++) {
                    u32 a[3][4], b[4][2];
#pragma unroll
                    for (int mi = 0; mi < 3; mi++)
                        ldA(a[mi], pA0 + 16 * mi * SXA + 8 * g8, SXA);
#pragma unroll
                    for (int nt = 0; nt < 4; nt++) {
                        ldB(b[nt], Wc + (32 * ng + 8 * nt + gq) * SXA + 2 * tq + 8 * g8);
#pragma unroll
                        for (int mi = 0; mi < 3; mi++) mma8(D[mi][nt], a[mi], b[nt]);
                    }
                }
            }
            // epilogue: add x-gates, LSTM cell update
#pragma unroll
            for (int mi = 0; mi < 3; mi++)
#pragma unroll
                for (int up = 0; up < 2; up++)
#pragma unroll
                    for (int r2 = 0; r2 < 2; r2++) {
                        int i = mi * 2 + r2;
                        float xa0 = up ? gb[i].x : ga[i].x;
                        float xa1 = up ? gb[i].y : ga[i].y;
                        float xb0 = up ? gb[i].z : ga[i].z;
                        float xb1 = up ? gb[i].w : ga[i].w;
                        float gi = D[mi][2 * up][2 * r2]     + xa0;
                        float gf = D[mi][2 * up][2 * r2 + 1] + xa1;
                        float gg = D[mi][2 * up + 1][2 * r2]     + xb0;
                        float go = D[mi][2 * up + 1][2 * r2 + 1] + xb1;
                        int s = ci * 12 + (mi * 2 + up) * 2 + r2;
                        float cc = siga(gf) * c_loc[s] + siga(gi) * tanha(gg);
                        c_loc[s] = cc;
                        h_loc[s] = __uint_as_float(tf32r(siga(go) * tanha(cc)));
                    }
        }
        __syncthreads();   // all Xs readers of this t done
        // write h(t): unit u = ci*32+8ng+4up+tq -> ilk col' = (4ci+ng)*8 + 2tq + up
#pragma unroll 1
        for (int ci = 0; ci < NCHG; ci++)
#pragma unroll
            for (int mi = 0; mi < 3; mi++)
#pragma unroll
                for (int up = 0; up < 2; up++)
#pragma unroll
                    for (int r2 = 0; r2 < 2; r2++)
                        Xs[(MB + 16 * mi + gq + 8 * r2) * SXA +
                           (4 * ci + ng) * 8 + 2 * tq + up] =
                            h_loc[ci * 12 + (mi * 2 + up) * 2 + r2];
        if (NCHG <= 2) __syncthreads();   // h visible for next t
    }

    // ---- FC: out = selfX (precomputed, bias folded) + h_final @ Wneigh^T ----
    constexpr int NTW = DOUT / 32, CG = DOUT / 4;
    cpa_wait0();
    __syncthreads();
    float* Ws = Wb[0];
    for (int e = tid; e < DOUT * G8; e += NT) {
        int r = e / G8, g8 = e % G8;
        uint4 A = tf32x4(Wn4[r * K4 + 2 * g8]);
        uint4 B = tf32x4(Wn4[r * K4 + 2 * g8 + 1]);
        uint4 o0, o1; ilsh(A, B, o0, o1);
        ((uint4*)(Ws + r * SXA + 8 * g8))[0] = o0;
        ((uint4*)(Ws + r * SXA + 8 * g8))[1] = o1;
    }
    __syncthreads();
    const float* pAf = Xs + (MB + gq) * SXA + 2 * tq;
    float2 sxv[3][4][2];
#pragma unroll
    for (int mi = 0; mi < 3; mi++)
#pragma unroll
        for (int r2 = 0; r2 < 2; r2++) {
            int nd = node0 + MB + 16 * mi + gq + 8 * r2;
            if (nd >= nN) nd = nN - 1;
            const float2* g2 = (const float2*)(gX +
                (size_t)nd * W + 4 * DIN + CG * ng + 2 * tq);
            for (int nt = 0; nt < NTW; nt++) sxv[mi][nt][r2] = g2[4 * nt];
        }
    float D[3][4][4];
#pragma unroll
    for (int mi = 0; mi < 3; mi++)
        for (int nt = 0; nt < NTW; nt++)
#pragma unroll
            for (int j = 0; j < 4; j++) D[mi][nt][j] = 0.f;
#pragma unroll 4
    for (int g8 = 0; g8 < G8; g8++) {
        u32 a[3][4], b[4][2];
#pragma unroll
        for (int mi = 0; mi < 3; mi++)
            ldA(a[mi], pAf + 16 * mi * SXA + 8 * g8, SXA);
        for (int nt = 0; nt < NTW; nt++) {
            ldB(b[nt], Ws + (CG * ng + 8 * nt + gq) * SXA + 2 * tq + 8 * g8);
#pragma unroll
            for (int mi = 0; mi < 3; mi++) mma8(D[mi][nt], a[mi], b[nt]);
        }
    }
    for (int nt = 0; nt < NTW; nt++) {
        int col = CG * ng + 8 * nt + 2 * tq;
#pragma unroll
        for (int mi = 0; mi < 3; mi++) {
            int r0 = node0 + MB + 16 * mi + gq;
            if (r0 < nN) {
                float v0 = D[mi][nt][0] + sxv[mi][nt][0].x;
                float v1 = D[mi][nt][1] + sxv[mi][nt][0].y;
                if (RELU) { v0 = fmaxf(v0, 0.f); v1 = fmaxf(v1, 0.f); }
                fout[r0 * DOUT + col] = v0; fout[r0 * DOUT + col + 1] = v1;
            }
            if (r0 + 8 < nN) {
                float v2 = D[mi][nt][2] + sxv[mi][nt][1].x;
                float v3 = D[mi][nt][3] + sxv[mi][nt][1].y;
                if (RELU) { v2 = fmaxf(v2, 0.f); v3 = fmaxf(v3, 0.f); }
                fout[(r0 + 8) * DOUT + col] = v2; fout[(r0 + 8) * DOUT + col + 1] = v3;
            }
        }
    }
}

extern "C" void kernel_launch(void* const* d_in, const int* in_sizes, int n_in,
                              void* d_out, int out_size) {
    const float* p  = (const float*)d_in[0];
    const int* nidx = (const int*)d_in[1];
    int nN = in_sizes[1] / KNB;

    float *fA, *fB, *gX, *Wp;
    cudaGetSymbolAddress((void**)&fA, g_fA);
    cudaGetSymbolAddress((void**)&fB, g_fB);
    cudaGetSymbolAddress((void**)&gX, g_gX);
    cudaGetSymbolAddress((void**)&Wp, g_Wp);

    auto smPre = [](int DIN, int DOUT) {
        return (144 * (DIN + 8) + 128 * (DIN + 8) + 4 * DIN + DOUT) * 4;
    };
    auto smRec = [](int DIN) {
        return (144 * (DIN + 8) + 2 * 128 * (DIN + 8)) * 4;
    };
    cudaFuncSetAttribute(pre_k<64, 128>,  cudaFuncAttributeMaxDynamicSharedMemorySize, smPre(64, 128));
    cudaFuncSetAttribute(pre_k<128, 128>, cudaFuncAttributeMaxDynamicSharedMemorySize, smPre(128, 128));
    cudaFuncSetAttribute(pre_k<128, 32>,  cudaFuncAttributeMaxDynamicSharedMemorySize, smPre(128, 32));
    cudaFuncSetAttribute(rec_k<64, 128, true>,  cudaFuncAttributeMaxDynamicSharedMemorySize, smRec(64));
    cudaFuncSetAttribute(rec_k<128, 128, true>, cudaFuncAttributeMaxDynamicSharedMemorySize, smRec(128));
    cudaFuncSetAttribute(rec_k<128, 32, false>, cudaFuncAttributeMaxDynamicSharedMemorySize, smRec(128));

    build_feat0<<<(nN * 64 + 255) / 256, 256>>>(p, fA, nN);

    int grid = (nN + 143) / 144;
    // layer 0
    pre_k<64, 128><<<grid, 384, smPre(64, 128)>>>(
        fA, (const float*)d_in[2], (const float*)d_in[4], (const float*)d_in[5],
        (const float*)d_in[6], (const float*)d_in[8], gX, nN);
    pack_k<<<(4 * 64 * 64 + 255) / 256, 256>>>((const float*)d_in[3], Wp, 64);
    rec_k<64, 128, true><<<grid, 384, smRec(64)>>>(
        gX, nidx, Wp, (const float*)d_in[7], fB, nN);
    // layer 1
    pre_k<128, 128><<<grid, 384, smPre(128, 128)>>>(
        fB, (const float*)d_in[9], (const float*)d_in[11], (const float*)d_in[12],
        (const float*)d_in[13], (const float*)d_in[15], gX, nN);
    pack_k<<<(4 * 128 * 128 + 255) / 256, 256>>>((const float*)d_in[10], Wp, 128);
    rec_k<128, 128, true><<<grid, 384, smRec(128)>>>(
        gX, nidx, Wp, (const float*)d_in[14], fA, nN);
    // layer 2
    pre_k<128, 32><<<grid, 384, smPre(128, 32)>>>(
        fA, (const float*)d_in[16], (const float*)d_in[18], (const float*)d_in[19],
        (const float*)d_in[20], (const float*)d_in[22], gX, nN);
    pack_k<<<(4 * 128 * 128 + 255) / 256, 256>>>((const float*)d_in[17], Wp, 128);
    rec_k<128, 32, false><<<grid, 384, smRec(128)>>>(
        gX, nidx, Wp, (const float*)d_in[21], (float*)d_out, nN);
}

// round 15
// speedup vs baseline: 1.1322x; 1.0850x over previous
#include <cuda_runtime.h>
#define KNB 16
typedef unsigned u32;

__device__ __align__(256) float g_fA[20096 * 128];
__device__ __align__(256) float g_fB[20096 * 128];
__device__ __align__(256) float g_gX[20096 * 640];
__device__ __align__(256) float g_Wp[512 * 128];
__device__ __align__(256) float g_Wq[640 * 128];

__device__ __forceinline__ float tanha(float x) {
    float r; asm("tanh.approx.f32 %0, %1;" : "=f"(r) : "f"(x)); return r;
}
__device__ __forceinline__ float siga(float x) {
    return fmaf(tanha(0.5f * x), 0.5f, 0.5f);
}
__device__ __forceinline__ u32 tf32r(float f) {
    u32 r; asm("cvt.rna.tf32.f32 %0, %1;" : "=r"(r) : "f"(f)); return r;
}
__device__ __forceinline__ uint4 tf32x4(float4 v) {
    return make_uint4(tf32r(v.x), tf32r(v.y), tf32r(v.z), tf32r(v.w));
}
__device__ __forceinline__ void mma8(float* d, const u32* a, const u32* b) {
    asm volatile("mma.sync.aligned.m16n8k8.row.col.f32.tf32.tf32.f32 "
        "{%0,%1,%2,%3},{%4,%5,%6,%7},{%8,%9},{%0,%1,%2,%3};"
        : "+f"(d[0]), "+f"(d[1]), "+f"(d[2]), "+f"(d[3])
        : "r"(a[0]), "r"(a[1]), "r"(a[2]), "r"(a[3]), "r"(b[0]), "r"(b[1]));
}
__device__ __forceinline__ u32 smem_u32(const void* p) {
    u32 a; asm("{ .reg .u64 t; cvta.to.shared.u64 t, %1; cvt.u32.u64 %0, t; }" : "=r"(a) : "l"(p)); return a;
}
__device__ __forceinline__ void cpa16(u32 dst, const void* src) {
    asm volatile("cp.async.cg.shared.global [%0], [%1], 16;" :: "r"(dst), "l"(src));
}
__device__ __forceinline__ void cpa_commit() { asm volatile("cp.async.commit_group;"); }
__device__ __forceinline__ void cpa_wait0()  { asm volatile("cp.async.wait_group 0;" ::: "memory"); }

// Gate-column permutation (see R10): thread (gq,tq) of warp ng owns all 4 gates
// of its units directly in its MMA output registers.
__device__ __forceinline__ int gmap(int c, int DIN) {
    int blk = c >> 5, w5 = c & 31;
    int nt = w5 >> 3, tq = (w5 >> 1) & 3, e = w5 & 1;
    return (2 * (nt & 1) + e) * DIN + blk * 8 + (nt >> 1) * 4 + tq;
}
// k-interleave within each 8-col group: [k0,k4,k1,k5,k2,k6,k3,k7]
__device__ __forceinline__ int ilk(int k) {
    return (k & ~7) + ((k & 3) << 1) + ((k >> 2) & 1);
}
__device__ __forceinline__ void ilsh(uint4 A, uint4 B, uint4& o0, uint4& o1) {
    o0 = make_uint4(A.x, B.x, A.y, B.y);
    o1 = make_uint4(A.z, B.z, A.w, B.w);
}
// A-fragment loader: 2x LDS.64 per m-tile
__device__ __forceinline__ void ldA(u32* a, const float* pa, int SXA) {
    float2 lo = *(const float2*)pa;
    float2 hi = *(const float2*)(pa + 8 * SXA);
    a[0] = __float_as_uint(lo.x); a[1] = __float_as_uint(hi.x);
    a[2] = __float_as_uint(lo.y); a[3] = __float_as_uint(hi.y);
}
__device__ __forceinline__ void ldB(u32* b, const float* pb) {
    float2 v = *(const float2*)pb;
    b[0] = __float_as_uint(v.x); b[1] = __float_as_uint(v.y);
}

__global__ void build_feat0(const float* __restrict__ p, float* __restrict__ f0, int nN) {
    int i = blockIdx.x * blockDim.x + threadIdx.x;
    if (i >= nN * 64) return;
    int node = i >> 6, k = i & 63;
    f0[i] = (k == 0) ? (16.0f / (float)nN) : p[node * 63 + (k - 1)];
}

// pre-pack Whh: tf32-rounded, gmap-permuted rows, ilk-interleaved cols
__global__ void pack_k(const float* __restrict__ Whh, float* __restrict__ Wp, int DIN) {
    int e = blockIdx.x * 256 + threadIdx.x;
    if (e >= 4 * DIN * DIN) return;
    int row = e / DIN, kk = e % DIN;
    Wp[row * DIN + ilk(kk)] =
        __uint_as_float(tf32r(Whh[gmap(row, DIN) * DIN + kk]));
}
// pre-pack [Wih(gmap) | Wself]: tf32 + ilk, contiguous DIN-float rows
__global__ void pack_pre(const float* __restrict__ Wih, const float* __restrict__ Wself,
                         float* __restrict__ Wq, int DIN, int DOUT) {
    int W = 4 * DIN + DOUT;
    int e = blockIdx.x * 256 + threadIdx.x;
    if (e >= W * DIN) return;
    int row = e / DIN, kk = e % DIN;
    float v = (row < 4 * DIN) ? Wih[gmap(row, DIN) * DIN + kk]
                              : Wself[(row - 4 * DIN) * DIN + kk];
    Wq[row * DIN + ilk(kk)] = __uint_as_float(tf32r(v));
}

// ---------------- precompute: gX[n] = feat[n] @ [Wih(permuted) | Wself]^T + bias ----------------
// cp.async double-buffered weight chunks from pre-packed Wq; STG.128 gate stores.
template <int DIN, int DOUT>
__global__ __launch_bounds__(384, 1)
void pre_k(const float* __restrict__ feat, const float* __restrict__ Wq,
           const float* __restrict__ bih, const float* __restrict__ bhh,
           const float* __restrict__ bo, float* __restrict__ gX, int nN)
{
    constexpr int TM = 144, NT = 384, K4 = DIN / 4, G8 = DIN / 8;
    constexpr int SXA = DIN + 8, W = 4 * DIN + DOUT;
    constexpr int NCHG = (4 * DIN) / 128;
    extern __shared__ float sm[];
    float* Xs = sm;
    float* Wb[2] = { sm + TM * SXA, sm + TM * SXA + 128 * SXA };
    float* CB = sm + (TM + 256) * SXA;

    const int tid = threadIdx.x, lane = tid & 31, w = tid >> 5;
    const int gq = lane >> 2, tq = lane & 3, mg = w % 3, ng = w / 3, MB = 48 * mg;
    const int node0 = blockIdx.x * TM;
    const u32 WbU[2] = { smem_u32(Wb[0]), smem_u32(Wb[1]) };
    const float4* fin4 = (const float4*)feat;

    for (int e = tid; e < 4 * DIN; e += NT) {
        int sr = gmap(e, DIN);
        CB[e] = bih[sr] + bhh[sr];
    }
    for (int e = tid; e < DOUT; e += NT) CB[4 * DIN + e] = bo[e];
    for (int e = tid; e < TM * G8; e += NT) {
        int row = e / G8, g8 = e % G8;
        int nd = node0 + row; if (nd >= nN) nd = nN - 1;
        uint4 A = tf32x4(fin4[nd * K4 + 2 * g8]);
        uint4 B = tf32x4(fin4[nd * K4 + 2 * g8 + 1]);
        uint4 o0, o1; ilsh(A, B, o0, o1);
        ((uint4*)(Xs + row * SXA + 8 * g8))[0] = o0;
        ((uint4*)(Xs + row * SXA + 8 * g8))[1] = o1;
    }
    // stage chunk 0
    {
        int CR0 = (W < 128) ? W : 128;
        for (int e = tid; e < CR0 * K4; e += NT) {
            int r = e / K4, c4 = e % K4;
            cpa16(WbU[0] + (u32)(r * SXA + c4 * 4) * 4u, Wq + r * DIN + c4 * 4);
        }
        cpa_commit();
    }
    const float* pA0 = Xs + (MB + gq) * SXA + 2 * tq;

    for (int c0 = 0; c0 < W; c0 += 128) {
        const int CR = (W - c0 < 128) ? (W - c0) : 128;
        const int NTW = CR / 32, CG = CR / 4;
        const int bi = (c0 >> 7) & 1;
        cpa_wait0();
        __syncthreads();   // chunk bi visible; prior readers of 1-bi done
        if (c0 + 128 < W) {
            int CRn = (W - c0 - 128 < 128) ? (W - c0 - 128) : 128;
            const float* src = Wq + (c0 + 128) * DIN;
            for (int e = tid; e < CRn * K4; e += NT) {
                int r = e / K4, c4 = e % K4;
                cpa16(WbU[1 - bi] + (u32)(r * SXA + c4 * 4) * 4u, src + r * DIN + c4 * 4);
            }
            cpa_commit();
        }
        float D[3][4][4];
        for (int nt = 0; nt < NTW; nt++) {
            float b0 = CB[c0 + CG * ng + 8 * nt + 2 * tq];
            float b1 = CB[c0 + CG * ng + 8 * nt + 2 * tq + 1];
#pragma unroll
            for (int mi = 0; mi < 3; mi++) {
                D[mi][nt][0] = b0; D[mi][nt][1] = b1;
                D[mi][nt][2] = b0; D[mi][nt][3] = b1;
            }
        }
#pragma unroll 4
        for (int g8 = 0; g8 < G8; g8++) {
            u32 a[3][4], b[4][2];
#pragma unroll
            for (int mi = 0; mi < 3; mi++)
                ldA(a[mi], pA0 + 16 * mi * SXA + 8 * g8, SXA);
            for (int nt = 0; nt < NTW; nt++) {
                ldB(b[nt], Wb[bi] + (CG * ng + 8 * nt + gq) * SXA + 2 * tq + 8 * g8);
#pragma unroll
                for (int mi = 0; mi < 3; mi++) mma8(D[mi][nt], a[mi], b[nt]);
            }
        }
        if (c0 < 4 * DIN) {
            // gate chunk (CR=128): thread's 8 cols are contiguous -> 2x STG.128 per row
            int ci = c0 >> 7;
            int colb = ng * (NCHG * 32) + ci * 32 + tq * 8;
#pragma unroll
            for (int mi = 0; mi < 3; mi++) {
                int r0 = node0 + MB + 16 * mi + gq;
                if (r0 < nN) {
                    *(float4*)(gX + (size_t)r0 * W + colb) =
                        make_float4(D[mi][0][0], D[mi][0][1], D[mi][1][0], D[mi][1][1]);
                    *(float4*)(gX + (size_t)r0 * W + colb + 4) =
                        make_float4(D[mi][2][0], D[mi][2][1], D[mi][3][0], D[mi][3][1]);
                }
                if (r0 + 8 < nN) {
                    *(float4*)(gX + (size_t)(r0 + 8) * W + colb) =
                        make_float4(D[mi][0][2], D[mi][0][3], D[mi][1][2], D[mi][1][3]);
                    *(float4*)(gX + (size_t)(r0 + 8) * W + colb + 4) =
                        make_float4(D[mi][2][2], D[mi][2][3], D[mi][3][2], D[mi][3][3]);
                }
            }
        } else {
            for (int nt = 0; nt < NTW; nt++) {
                int col = c0 + CG * ng + 8 * nt + 2 * tq;
#pragma unroll
                for (int mi = 0; mi < 3; mi++) {
                    int r0 = node0 + MB + 16 * mi + gq;
                    if (r0 < nN) {
                        gX[(size_t)r0 * W + col] = D[mi][nt][0];
                        gX[(size_t)r0 * W + col + 1] = D[mi][nt][1];
                    }
                    if (r0 + 8 < nN) {
                        gX[(size_t)(r0 + 8) * W + col] = D[mi][nt][2];
                        gX[(size_t)(r0 + 8) * W + col + 1] = D[mi][nt][3];
                    }
                }
            }
        }
    }
}

// ---------------- recurrent (unchanged from R14) ----------------
template <int DIN, int DOUT, bool RELU>
__global__ __launch_bounds__(384, 1)
void rec_k(const float* __restrict__ gX, const int* __restrict__ nidx,
           const float* __restrict__ Wp, const float* __restrict__ Wneigh,
           float* __restrict__ fout, int nN)
{
    constexpr int TM = 144, NT = 384, K4 = DIN / 4, G8 = DIN / 8, SXA = DIN + 8;
    constexpr int W = 4 * DIN + DOUT, NCHG = (4 * DIN) / 128;
    extern __shared__ float sm[];
    float* Xs = sm;                              // TM x SXA : h (tf32, ilk layout)
    float* Wb[2] = { sm + TM * SXA, sm + TM * SXA + 128 * SXA };

    const int tid = threadIdx.x, lane = tid & 31, w = tid >> 5;
    const int gq = lane >> 2, tq = lane & 3, mg = w % 3, ng = w / 3, MB = 48 * mg;
    const int node0 = blockIdx.x * TM;
    const u32 WbU[2] = { smem_u32(Wb[0]), smem_u32(Wb[1]) };
    const float4* Wn4 = (const float4*)Wneigh;

    float c_loc[NCHG * 12], h_loc[NCHG * 12];
#pragma unroll
    for (int i = 0; i < NCHG * 12; i++) c_loc[i] = 0.f;

    if (NCHG <= 2) {
        for (int c = 0; c < NCHG; c++) {
            const float* src = Wp + c * 128 * DIN;
            for (int e = tid; e < 128 * K4; e += NT) {
                int row = e / K4, c4 = e % K4;
                cpa16(WbU[c] + (u32)(row * SXA + c4 * 4) * 4u, src + row * DIN + c4 * 4);
            }
        }
        cpa_commit();
        cpa_wait0();
        __syncthreads();
    } else {
        const float* src = Wp;
        for (int e = tid; e < 128 * K4; e += NT) {
            int row = e / K4, c4 = e % K4;
            cpa16(WbU[0] + (u32)(row * SXA + c4 * 4) * 4u, src + row * DIN + c4 * 4);
        }
        cpa_commit();
    }

    for (int t = 0; t < KNB; t++) {
        int srcs[6];
#pragma unroll
        for (int mi = 0; mi < 3; mi++)
#pragma unroll
            for (int r2 = 0; r2 < 2; r2++) {
                int nd = node0 + MB + 16 * mi + gq + 8 * r2;
                if (nd >= nN) nd = nN - 1;
                srcs[mi * 2 + r2] = nidx[nd * KNB + t];
            }
        const float* pA0 = Xs + (MB + gq) * SXA + 2 * tq;

#pragma unroll 1
        for (int ci = 0; ci < NCHG; ci++) {
            float4 ga[6], gb[6];
#pragma unroll
            for (int i = 0; i < 6; i++) {
                const float4* g4 = (const float4*)(gX +
                    (size_t)srcs[i] * W + (size_t)(ng * NCHG + ci) * 32 + tq * 8);
                ga[i] = g4[0];
                gb[i] = g4[1];
            }
            if (NCHG > 2 && t > 0) {
                cpa_wait0();
                __syncthreads();
                int cn = (ci + 1 < NCHG) ? ci + 1 : 0;
                const float* src = Wp + cn * 128 * DIN;
                u32 dstU = WbU[(ci + 1) & 1];
                for (int e = tid; e < 128 * K4; e += NT) {
                    int row = e / K4, c4 = e % K4;
                    cpa16(dstU + (u32)(row * SXA + c4 * 4) * 4u, src + row * DIN + c4 * 4);
                }
                cpa_commit();
            }
            float D[3][4][4];
#pragma unroll
            for (int mi = 0; mi < 3; mi++)
#pragma unroll
                for (int nt = 0; nt < 4; nt++)
#pragma unroll
                    for (int j = 0; j < 4; j++) D[mi][nt][j] = 0.f;
            if (t > 0) {
                const float* Wc = Wb[(NCHG > 2) ? (ci & 1) : ci];
#pragma unroll 4
                for (int g8 = 0; g8 < G8; g8++) {
                    u32 a[3][4], b[4][2];
#pragma unroll
                    for (int mi = 0; mi < 3; mi++)
                        ldA(a[mi], pA0 + 16 * mi * SXA + 8 * g8, SXA);
#pragma unroll
                    for (int nt = 0; nt < 4; nt++) {
                        ldB(b[nt], Wc + (32 * ng + 8 * nt + gq) * SXA + 2 * tq + 8 * g8);
#pragma unroll
                        for (int mi = 0; mi < 3; mi++) mma8(D[mi][nt], a[mi], b[nt]);
                    }
                }
            }
#pragma unroll
            for (int mi = 0; mi < 3; mi++)
#pragma unroll
                for (int up = 0; up < 2; up++)
#pragma unroll
                    for (int r2 = 0; r2 < 2; r2++) {
                        int i = mi * 2 + r2;
                        float xa0 = up ? gb[i].x : ga[i].x;
                        float xa1 = up ? gb[i].y : ga[i].y;
                        float xb0 = up ? gb[i].z : ga[i].z;
                        float xb1 = up ? gb[i].w : ga[i].w;
                        float gi = D[mi][2 * up][2 * r2]     + xa0;
                        float gf = D[mi][2 * up][2 * r2 + 1] + xa1;
                        float gg = D[mi][2 * up + 1][2 * r2]     + xb0;
                        float go = D[mi][2 * up + 1][2 * r2 + 1] + xb1;
                        int s = ci * 12 + (mi * 2 + up) * 2 + r2;
                        float cc = siga(gf) * c_loc[s] + siga(gi) * tanha(gg);
                        c_loc[s] = cc;
                        h_loc[s] = __uint_as_float(tf32r(siga(go) * tanha(cc)));
                    }
        }
        __syncthreads();
#pragma unroll 1
        for (int ci = 0; ci < NCHG; ci++)
#pragma unroll
            for (int mi = 0; mi < 3; mi++)
#pragma unroll
                for (int up = 0; up < 2; up++)
#pragma unroll
                    for (int r2 = 0; r2 < 2; r2++)
                        Xs[(MB + 16 * mi + gq + 8 * r2) * SXA +
                           (4 * ci + ng) * 8 + 2 * tq + up] =
                            h_loc[ci * 12 + (mi * 2 + up) * 2 + r2];
        if (NCHG <= 2) __syncthreads();
    }

    // ---- FC: out = selfX (precomputed, bias folded) + h_final @ Wneigh^T ----
    constexpr int NTW = DOUT / 32, CG = DOUT / 4;
    cpa_wait0();
    __syncthreads();
    float* Ws = Wb[0];
    for (int e = tid; e < DOUT * G8; e += NT) {
        int r = e / G8, g8 = e % G8;
        uint4 A = tf32x4(Wn4[r * K4 + 2 * g8]);
        uint4 B = tf32x4(Wn4[r * K4 + 2 * g8 + 1]);
        uint4 o0, o1; ilsh(A, B, o0, o1);
        ((uint4*)(Ws + r * SXA + 8 * g8))[0] = o0;
        ((uint4*)(Ws + r * SXA + 8 * g8))[1] = o1;
    }
    __syncthreads();
    const float* pAf = Xs + (MB + gq) * SXA + 2 * tq;
    float2 sxv[3][4][2];
#pragma unroll
    for (int mi = 0; mi < 3; mi++)
#pragma unroll
        for (int r2 = 0; r2 < 2; r2++) {
            int nd = node0 + MB + 16 * mi + gq + 8 * r2;
            if (nd >= nN) nd = nN - 1;
            const float2* g2 = (const float2*)(gX +
                (size_t)nd * W + 4 * DIN + CG * ng + 2 * tq);
            for (int nt = 0; nt < NTW; nt++) sxv[mi][nt][r2] = g2[4 * nt];
        }
    float D[3][4][4];
#pragma unroll
    for (int mi = 0; mi < 3; mi++)
        for (int nt = 0; nt < NTW; nt++)
#pragma unroll
            for (int j = 0; j < 4; j++) D[mi][nt][j] = 0.f;
#pragma unroll 4
    for (int g8 = 0; g8 < G8; g8++) {
        u32 a[3][4], b[4][2];
#pragma unroll
        for (int mi = 0; mi < 3; mi++)
            ldA(a[mi], pAf + 16 * mi * SXA + 8 * g8, SXA);
        for (int nt = 0; nt < NTW; nt++) {
            ldB(b[nt], Ws + (CG * ng + 8 * nt + gq) * SXA + 2 * tq + 8 * g8);
#pragma unroll
            for (int mi = 0; mi < 3; mi++) mma8(D[mi][nt], a[mi], b[nt]);
        }
    }
    for (int nt = 0; nt < NTW; nt++) {
        int col = CG * ng + 8 * nt + 2 * tq;
#pragma unroll
        for (int mi = 0; mi < 3; mi++) {
            int r0 = node0 + MB + 16 * mi + gq;
            if (r0 < nN) {
                float v0 = D[mi][nt][0] + sxv[mi][nt][0].x;
                float v1 = D[mi][nt][1] + sxv[mi][nt][0].y;
                if (RELU) { v0 = fmaxf(v0, 0.f); v1 = fmaxf(v1, 0.f); }
                fout[r0 * DOUT + col] = v0; fout[r0 * DOUT + col + 1] = v1;
            }
            if (r0 + 8 < nN) {
                float v2 = D[mi][nt][2] + sxv[mi][nt][1].x;
                float v3 = D[mi][nt][3] + sxv[mi][nt][1].y;
                if (RELU) { v2 = fmaxf(v2, 0.f); v3 = fmaxf(v3, 0.f); }
                fout[(r0 + 8) * DOUT + col] = v2; fout[(r0 + 8) * DOUT + col + 1] = v3;
            }
        }
    }
}

extern "C" void kernel_launch(void* const* d_in, const int* in_sizes, int n_in,
                              void* d_out, int out_size) {
    const float* p  = (const float*)d_in[0];
    const int* nidx = (const int*)d_in[1];
    int nN = in_sizes[1] / KNB;

    float *fA, *fB, *gX, *Wp, *Wq;
    cudaGetSymbolAddress((void**)&fA, g_fA);
    cudaGetSymbolAddress((void**)&fB, g_fB);
    cudaGetSymbolAddress((void**)&gX, g_gX);
    cudaGetSymbolAddress((void**)&Wp, g_Wp);
    cudaGetSymbolAddress((void**)&Wq, g_Wq);

    auto smPre = [](int DIN, int DOUT) {
        return ((144 + 256) * (DIN + 8) + 4 * DIN + DOUT) * 4;
    };
    auto smRec = [](int DIN) {
        return (144 * (DIN + 8) + 2 * 128 * (DIN + 8)) * 4;
    };
    cudaFuncSetAttribute(pre_k<64, 128>,  cudaFuncAttributeMaxDynamicSharedMemorySize, smPre(64, 128));
    cudaFuncSetAttribute(pre_k<128, 128>, cudaFuncAttributeMaxDynamicSharedMemorySize, smPre(128, 128));
    cudaFuncSetAttribute(pre_k<128, 32>,  cudaFuncAttributeMaxDynamicSharedMemorySize, smPre(128, 32));
    cudaFuncSetAttribute(rec_k<64, 128, true>,  cudaFuncAttributeMaxDynamicSharedMemorySize, smRec(64));
    cudaFuncSetAttribute(rec_k<128, 128, true>, cudaFuncAttributeMaxDynamicSharedMemorySize, smRec(128));
    cudaFuncSetAttribute(rec_k<128, 32, false>, cudaFuncAttributeMaxDynamicSharedMemorySize, smRec(128));

    build_feat0<<<(nN * 64 + 255) / 256, 256>>>(p, fA, nN);

    int grid = (nN + 143) / 144;
    // layer 0
    pack_pre<<<(384 * 64 + 255) / 256, 256>>>((const float*)d_in[2], (const float*)d_in[6], Wq, 64, 128);
    pack_k<<<(4 * 64 * 64 + 255) / 256, 256>>>((const float*)d_in[3], Wp, 64);
    pre_k<64, 128><<<grid, 384, smPre(64, 128)>>>(
        fA, Wq, (const float*)d_in[4], (const float*)d_in[5],
        (const float*)d_in[8], gX, nN);
    rec_k<64, 128, true><<<grid, 384, smRec(64)>>>(
        gX, nidx, Wp, (const float*)d_in[7], fB, nN);
    // layer 1
    pack_pre<<<(640 * 128 + 255) / 256, 256>>>((const float*)d_in[9], (const float*)d_in[13], Wq, 128, 128);
    pack_k<<<(4 * 128 * 128 + 255) / 256, 256>>>((const float*)d_in[10], Wp, 128);
    pre_k<128, 128><<<grid, 384, smPre(128, 128)>>>(
        fB, Wq, (const float*)d_in[11], (const float*)d_in[12],
        (const float*)d_in[15], gX, nN);
    rec_k<128, 128, true><<<grid, 384, smRec(128)>>>(
        gX, nidx, Wp, (const float*)d_in[14], fA, nN);
    // layer 2
    pack_pre<<<(544 * 128 + 255) / 256, 256>>>((const float*)d_in[16], (const float*)d_in[20], Wq, 128, 32);
    pack_k<<<(4 * 128 * 128 + 255) / 256, 256>>>((const float*)d_in[17], Wp, 128);
    pre_k<128, 32><<<grid, 384, smPre(128, 32)>>>(
        fA, Wq, (const float*)d_in[18], (const float*)d_in[19],
        (const float*)d_in[22], gX, nN);
    rec_k<128, 32, false><<<grid, 384, smRec(128)>>>(
        gX, nidx, Wp, (const float*)d_in[21], (float*)d_out, nN);
}

// round 16
// speedup vs baseline: 1.1456x; 1.0118x over previous
#include <cuda_runtime.h>
#define KNB 16
typedef unsigned u32;

__device__ __align__(256) float g_fA[20096 * 128];
__device__ __align__(256) float g_fB[20096 * 128];
__device__ __align__(256) float g_gX[20096 * 640];
__device__ __align__(256) float g_Wp[512 * 128];
__device__ __align__(256) float g_Wq[640 * 128];

__device__ __forceinline__ float tanha(float x) {
    float r; asm("tanh.approx.f32 %0, %1;" : "=f"(r) : "f"(x)); return r;
}
__device__ __forceinline__ float siga(float x) {
    return fmaf(tanha(0.5f * x), 0.5f, 0.5f);
}
__device__ __forceinline__ u32 tf32r(float f) {
    u32 r; asm("cvt.rna.tf32.f32 %0, %1;" : "=r"(r) : "f"(f)); return r;
}
__device__ __forceinline__ uint4 tf32x4(float4 v) {
    return make_uint4(tf32r(v.x), tf32r(v.y), tf32r(v.z), tf32r(v.w));
}
__device__ __forceinline__ void mma8(float* d, const u32* a, const u32* b) {
    asm volatile("mma.sync.aligned.m16n8k8.row.col.f32.tf32.tf32.f32 "
        "{%0,%1,%2,%3},{%4,%5,%6,%7},{%8,%9},{%0,%1,%2,%3};"
        : "+f"(d[0]), "+f"(d[1]), "+f"(d[2]), "+f"(d[3])
        : "r"(a[0]), "r"(a[1]), "r"(a[2]), "r"(a[3]), "r"(b[0]), "r"(b[1]));
}
__device__ __forceinline__ u32 smem_u32(const void* p) {
    u32 a; asm("{ .reg .u64 t; cvta.to.shared.u64 t, %1; cvt.u32.u64 %0, t; }" : "=r"(a) : "l"(p)); return a;
}
__device__ __forceinline__ void cpa16(u32 dst, const void* src) {
    asm volatile("cp.async.cg.shared.global [%0], [%1], 16;" :: "r"(dst), "l"(src));
}
__device__ __forceinline__ void cpa_commit() { asm volatile("cp.async.commit_group;"); }
__device__ __forceinline__ void cpa_wait0()  { asm volatile("cp.async.wait_group 0;" ::: "memory"); }

// Gate-column permutation (see R10): thread (gq,tq) of warp ng owns all 4 gates
// of its units directly in its MMA output registers.
__device__ __forceinline__ int gmap(int c, int DIN) {
    int blk = c >> 5, w5 = c & 31;
    int nt = w5 >> 3, tq = (w5 >> 1) & 3, e = w5 & 1;
    return (2 * (nt & 1) + e) * DIN + blk * 8 + (nt >> 1) * 4 + tq;
}
// k-interleave within each 8-col group: [k0,k4,k1,k5,k2,k6,k3,k7]
__device__ __forceinline__ int ilk(int k) {
    return (k & ~7) + ((k & 3) << 1) + ((k >> 2) & 1);
}
__device__ __forceinline__ void ilsh(uint4 A, uint4 B, uint4& o0, uint4& o1) {
    o0 = make_uint4(A.x, B.x, A.y, B.y);
    o1 = make_uint4(A.z, B.z, A.w, B.w);
}
// A-fragment loader: 2x LDS.64 per m-tile
__device__ __forceinline__ void ldA(u32* a, const float* pa, int SXA) {
    float2 lo = *(const float2*)pa;
    float2 hi = *(const float2*)(pa + 8 * SXA);
    a[0] = __float_as_uint(lo.x); a[1] = __float_as_uint(hi.x);
    a[2] = __float_as_uint(lo.y); a[3] = __float_as_uint(hi.y);
}
__device__ __forceinline__ void ldB(u32* b, const float* pb) {
    float2 v = *(const float2*)pb;
    b[0] = __float_as_uint(v.x); b[1] = __float_as_uint(v.y);
}

__global__ void build_feat0(const float* __restrict__ p, float* __restrict__ f0, int nN) {
    int i = blockIdx.x * blockDim.x + threadIdx.x;
    if (i >= nN * 64) return;
    int node = i >> 6, k = i & 63;
    f0[i] = (k == 0) ? (16.0f / (float)nN) : p[node * 63 + (k - 1)];
}

// merged pack: Wq = [Wih(gmap)|Wself] tf32+ilk ; Wp = Whh(gmap) tf32+ilk
__global__ void pack_all(const float* __restrict__ Wih, const float* __restrict__ Whh,
                         const float* __restrict__ Wself,
                         float* __restrict__ Wq, float* __restrict__ Wp,
                         int DIN, int DOUT) {
    int Wn = 4 * DIN + DOUT;
    int tot = (Wn + 4 * DIN) * DIN;
    int e = blockIdx.x * 256 + threadIdx.x;
    if (e >= tot) return;
    int row = e / DIN, kk = e % DIN;
    if (row < Wn) {
        float v = (row < 4 * DIN) ? Wih[gmap(row, DIN) * DIN + kk]
                                  : Wself[(row - 4 * DIN) * DIN + kk];
        Wq[row * DIN + ilk(kk)] = __uint_as_float(tf32r(v));
    } else {
        int r2 = row - Wn;
        Wp[r2 * DIN + ilk(kk)] = __uint_as_float(tf32r(Whh[gmap(r2, DIN) * DIN + kk]));
    }
}

// ---------------- precompute: gX[n] = feat[n] @ [Wih(permuted) | Wself]^T + bias ----------------
template <int DIN, int DOUT>
__global__ __launch_bounds__(384, 1)
void pre_k(const float* __restrict__ feat, const float* __restrict__ Wq,
           const float* __restrict__ bih, const float* __restrict__ bhh,
           const float* __restrict__ bo, float* __restrict__ gX, int nN)
{
    constexpr int TM = 144, NT = 384, K4 = DIN / 4, G8 = DIN / 8;
    constexpr int SXA = DIN + 8, W = 4 * DIN + DOUT;
    constexpr int NCHG = (4 * DIN) / 128;
    extern __shared__ float sm[];
    float* Xs = sm;
    float* Wb[2] = { sm + TM * SXA, sm + TM * SXA + 128 * SXA };
    float* CB = sm + (TM + 256) * SXA;

    const int tid = threadIdx.x, lane = tid & 31, w = tid >> 5;
    const int gq = lane >> 2, tq = lane & 3, mg = w % 3, ng = w / 3, MB = 48 * mg;
    const int node0 = blockIdx.x * TM;
    const u32 WbU[2] = { smem_u32(Wb[0]), smem_u32(Wb[1]) };
    const float4* fin4 = (const float4*)feat;

    for (int e = tid; e < 4 * DIN; e += NT) {
        int sr = gmap(e, DIN);
        CB[e] = bih[sr] + bhh[sr];
    }
    for (int e = tid; e < DOUT; e += NT) CB[4 * DIN + e] = bo[e];
    for (int e = tid; e < TM * G8; e += NT) {
        int row = e / G8, g8 = e % G8;
        int nd = node0 + row; if (nd >= nN) nd = nN - 1;
        uint4 A = tf32x4(fin4[nd * K4 + 2 * g8]);
        uint4 B = tf32x4(fin4[nd * K4 + 2 * g8 + 1]);
        uint4 o0, o1; ilsh(A, B, o0, o1);
        ((uint4*)(Xs + row * SXA + 8 * g8))[0] = o0;
        ((uint4*)(Xs + row * SXA + 8 * g8))[1] = o1;
    }
    {
        int CR0 = (W < 128) ? W : 128;
        for (int e = tid; e < CR0 * K4; e += NT) {
            int r = e / K4, c4 = e % K4;
            cpa16(WbU[0] + (u32)(r * SXA + c4 * 4) * 4u, Wq + r * DIN + c4 * 4);
        }
        cpa_commit();
    }
    const float* pA0 = Xs + (MB + gq) * SXA + 2 * tq;

    for (int c0 = 0; c0 < W; c0 += 128) {
        const int CR = (W - c0 < 128) ? (W - c0) : 128;
        const int NTW = CR / 32, CG = CR / 4;
        const int bi = (c0 >> 7) & 1;
        cpa_wait0();
        __syncthreads();
        if (c0 + 128 < W) {
            int CRn = (W - c0 - 128 < 128) ? (W - c0 - 128) : 128;
            const float* src = Wq + (c0 + 128) * DIN;
            for (int e = tid; e < CRn * K4; e += NT) {
                int r = e / K4, c4 = e % K4;
                cpa16(WbU[1 - bi] + (u32)(r * SXA + c4 * 4) * 4u, src + r * DIN + c4 * 4);
            }
            cpa_commit();
        }
        float D[3][4][4];
        for (int nt = 0; nt < NTW; nt++) {
            float b0 = CB[c0 + CG * ng + 8 * nt + 2 * tq];
            float b1 = CB[c0 + CG * ng + 8 * nt + 2 * tq + 1];
#pragma unroll
            for (int mi = 0; mi < 3; mi++) {
                D[mi][nt][0] = b0; D[mi][nt][1] = b1;
                D[mi][nt][2] = b0; D[mi][nt][3] = b1;
            }
        }
#pragma unroll 8
        for (int g8 = 0; g8 < G8; g8++) {
            u32 a[3][4], b[4][2];
#pragma unroll
            for (int mi = 0; mi < 3; mi++)
                ldA(a[mi], pA0 + 16 * mi * SXA + 8 * g8, SXA);
            for (int nt = 0; nt < NTW; nt++) {
                ldB(b[nt], Wb[bi] + (CG * ng + 8 * nt + gq) * SXA + 2 * tq + 8 * g8);
#pragma unroll
                for (int mi = 0; mi < 3; mi++) mma8(D[mi][nt], a[mi], b[nt]);
            }
        }
        if (c0 < 4 * DIN) {
            int ci = c0 >> 7;
            int colb = ng * (NCHG * 32) + ci * 32 + tq * 8;
#pragma unroll
            for (int mi = 0; mi < 3; mi++) {
                int r0 = node0 + MB + 16 * mi + gq;
                if (r0 < nN) {
                    *(float4*)(gX + (size_t)r0 * W + colb) =
                        make_float4(D[mi][0][0], D[mi][0][1], D[mi][1][0], D[mi][1][1]);
                    *(float4*)(gX + (size_t)r0 * W + colb + 4) =
                        make_float4(D[mi][2][0], D[mi][2][1], D[mi][3][0], D[mi][3][1]);
                }
                if (r0 + 8 < nN) {
                    *(float4*)(gX + (size_t)(r0 + 8) * W + colb) =
                        make_float4(D[mi][0][2], D[mi][0][3], D[mi][1][2], D[mi][1][3]);
                    *(float4*)(gX + (size_t)(r0 + 8) * W + colb + 4) =
                        make_float4(D[mi][2][2], D[mi][2][3], D[mi][3][2], D[mi][3][3]);
                }
            }
        } else {
            for (int nt = 0; nt < NTW; nt++) {
                int col = c0 + CG * ng + 8 * nt + 2 * tq;
#pragma unroll
                for (int mi = 0; mi < 3; mi++) {
                    int r0 = node0 + MB + 16 * mi + gq;
                    if (r0 < nN) {
                        gX[(size_t)r0 * W + col] = D[mi][nt][0];
                        gX[(size_t)r0 * W + col + 1] = D[mi][nt][1];
                    }
                    if (r0 + 8 < nN) {
                        gX[(size_t)(r0 + 8) * W + col] = D[mi][nt][2];
                        gX[(size_t)(r0 + 8) * W + col + 1] = D[mi][nt][3];
                    }
                }
            }
        }
    }
}

// ---------------- recurrent ----------------
// NCHG==2 (DIN=64): Xs double-buffered + both Whh chunks resident -> 1 barrier/t,
//                   h written directly (no h_loc).
// NCHG==4 (DIN=128): single Xs + h_loc, cp.async double-buffered chunk pipeline.
template <int DIN, int DOUT, bool RELU>
__global__ __launch_bounds__(384, 1)
void rec_k(const float* __restrict__ gX, const int* __restrict__ nidx,
           const float* __restrict__ Wp, const float* __restrict__ Wneigh,
           float* __restrict__ fout, int nN)
{
    constexpr int TM = 144, NT = 384, K4 = DIN / 4, G8 = DIN / 8, SXA = DIN + 8;
    constexpr int W = 4 * DIN + DOUT, NCHG = (4 * DIN) / 128;
    constexpr int NXB = (NCHG <= 2) ? 2 : 1;
    extern __shared__ float sm[];
    float* XsB[2] = { sm, sm + (NXB - 1) * TM * SXA };  // alias when single-buffered
    float* WbBase = sm + NXB * TM * SXA;
    float* Wb[2] = { WbBase, WbBase + 128 * SXA };

    const int tid = threadIdx.x, lane = tid & 31, w = tid >> 5;
    const int gq = lane >> 2, tq = lane & 3, mg = w % 3, ng = w / 3, MB = 48 * mg;
    const int node0 = blockIdx.x * TM;
    const u32 WbU[2] = { smem_u32(Wb[0]), smem_u32(Wb[1]) };
    const float4* Wn4 = (const float4*)Wneigh;

    float c_loc[NCHG * 12], h_loc[NCHG * 12];
#pragma unroll
    for (int i = 0; i < NCHG * 12; i++) c_loc[i] = 0.f;

    if (NCHG <= 2) {
        for (int c = 0; c < NCHG; c++) {
            const float* src = Wp + c * 128 * DIN;
            for (int e = tid; e < 128 * K4; e += NT) {
                int row = e / K4, c4 = e % K4;
                cpa16(WbU[c] + (u32)(row * SXA + c4 * 4) * 4u, src + row * DIN + c4 * 4);
            }
        }
        cpa_commit();
        cpa_wait0();
        __syncthreads();
    } else {
        const float* src = Wp;
        for (int e = tid; e < 128 * K4; e += NT) {
            int row = e / K4, c4 = e % K4;
            cpa16(WbU[0] + (u32)(row * SXA + c4 * 4) * 4u, src + row * DIN + c4 * 4);
        }
        cpa_commit();
    }

    for (int t = 0; t < KNB; t++) {
        int srcs[6];
#pragma unroll
        for (int mi = 0; mi < 3; mi++)
#pragma unroll
            for (int r2 = 0; r2 < 2; r2++) {
                int nd = node0 + MB + 16 * mi + gq + 8 * r2;
                if (nd >= nN) nd = nN - 1;
                srcs[mi * 2 + r2] = nidx[nd * KNB + t];
            }
        const float* Xc = XsB[t & (NXB - 1)];
        float* Xn = XsB[(t + 1) & (NXB - 1)];
        const float* pA0 = Xc + (MB + gq) * SXA + 2 * tq;

#pragma unroll 1
        for (int ci = 0; ci < NCHG; ci++) {
            float4 ga[6], gb[6];
#pragma unroll
            for (int i = 0; i < 6; i++) {
                const float4* g4 = (const float4*)(gX +
                    (size_t)srcs[i] * W + (size_t)(ng * NCHG + ci) * 32 + tq * 8);
                ga[i] = g4[0];
                gb[i] = g4[1];
            }
            if (NCHG > 2 && t > 0) {
                cpa_wait0();
                __syncthreads();
                int cn = (ci + 1 < NCHG) ? ci + 1 : 0;
                const float* src = Wp + cn * 128 * DIN;
                u32 dstU = WbU[(ci + 1) & 1];
                for (int e = tid; e < 128 * K4; e += NT) {
                    int row = e / K4, c4 = e % K4;
                    cpa16(dstU + (u32)(row * SXA + c4 * 4) * 4u, src + row * DIN + c4 * 4);
                }
                cpa_commit();
            }
            float D[3][4][4];
#pragma unroll
            for (int mi = 0; mi < 3; mi++)
#pragma unroll
                for (int nt = 0; nt < 4; nt++)
#pragma unroll
                    for (int j = 0; j < 4; j++) D[mi][nt][j] = 0.f;
            if (t > 0) {
                const float* Wc = Wb[(NCHG > 2) ? (ci & 1) : ci];
#pragma unroll 8
                for (int g8 = 0; g8 < G8; g8++) {
                    u32 a[3][4], b[4][2];
#pragma unroll
                    for (int mi = 0; mi < 3; mi++)
                        ldA(a[mi], pA0 + 16 * mi * SXA + 8 * g8, SXA);
#pragma unroll
                    for (int nt = 0; nt < 4; nt++) {
                        ldB(b[nt], Wc + (32 * ng + 8 * nt + gq) * SXA + 2 * tq + 8 * g8);
#pragma unroll
                        for (int mi = 0; mi < 3; mi++) mma8(D[mi][nt], a[mi], b[nt]);
                    }
                }
            }
#pragma unroll
            for (int mi = 0; mi < 3; mi++)
#pragma unroll
                for (int up = 0; up < 2; up++)
#pragma unroll
                    for (int r2 = 0; r2 < 2; r2++) {
                        int i = mi * 2 + r2;
                        float xa0 = up ? gb[i].x : ga[i].x;
                        float xa1 = up ? gb[i].y : ga[i].y;
                        float xb0 = up ? gb[i].z : ga[i].z;
                        float xb1 = up ? gb[i].w : ga[i].w;
                        float gi = D[mi][2 * up][2 * r2]     + xa0;
                        float gf = D[mi][2 * up][2 * r2 + 1] + xa1;
                        float gg = D[mi][2 * up + 1][2 * r2]     + xb0;
                        float go = D[mi][2 * up + 1][2 * r2 + 1] + xb1;
                        int s = ci * 12 + (mi * 2 + up) * 2 + r2;
                        float cc = siga(gf) * c_loc[s] + siga(gi) * tanha(gg);
                        c_loc[s] = cc;
                        float hv = __uint_as_float(tf32r(siga(go) * tanha(cc)));
                        if (NCHG <= 2) {
                            Xn[(MB + 16 * mi + gq + 8 * r2) * SXA +
                               (4 * ci + ng) * 8 + 2 * tq + up] = hv;
                        } else {
                            h_loc[s] = hv;
                        }
                    }
        }
        if (NCHG <= 2) {
            __syncthreads();   // Xn complete; Xc reads done -> flip
        } else {
            __syncthreads();
#pragma unroll 1
            for (int ci = 0; ci < NCHG; ci++)
#pragma unroll
                for (int mi = 0; mi < 3; mi++)
#pragma unroll
                    for (int up = 0; up < 2; up++)
#pragma unroll
                        for (int r2 = 0; r2 < 2; r2++)
                            ((float*)XsB[0])[(MB + 16 * mi + gq + 8 * r2) * SXA +
                               (4 * ci + ng) * 8 + 2 * tq + up] =
                                h_loc[ci * 12 + (mi * 2 + up) * 2 + r2];
        }
    }

    // ---- FC: out = selfX (precomputed, bias folded) + h_final @ Wneigh^T ----
    constexpr int NTW = DOUT / 32, CG = DOUT / 4;
    const float* Xf = XsB[KNB & (NXB - 1)];
    cpa_wait0();
    __syncthreads();
    float* Ws = Wb[0];
    for (int e = tid; e < DOUT * G8; e += NT) {
        int r = e / G8, g8 = e % G8;
        uint4 A = tf32x4(Wn4[r * K4 + 2 * g8]);
        uint4 B = tf32x4(Wn4[r * K4 + 2 * g8 + 1]);
        uint4 o0, o1; ilsh(A, B, o0, o1);
        ((uint4*)(Ws + r * SXA + 8 * g8))[0] = o0;
        ((uint4*)(Ws + r * SXA + 8 * g8))[1] = o1;
    }
    __syncthreads();
    const float* pAf = Xf + (MB + gq) * SXA + 2 * tq;
    float2 sxv[3][4][2];
#pragma unroll
    for (int mi = 0; mi < 3; mi++)
#pragma unroll
        for (int r2 = 0; r2 < 2; r2++) {
            int nd = node0 + MB + 16 * mi + gq + 8 * r2;
            if (nd >= nN) nd = nN - 1;
            const float2* g2 = (const float2*)(gX +
                (size_t)nd * W + 4 * DIN + CG * ng + 2 * tq);
            for (int nt = 0; nt < NTW; nt++) sxv[mi][nt][r2] = g2[4 * nt];
        }
    float D[3][4][4];
#pragma unroll
    for (int mi = 0; mi < 3; mi++)
        for (int nt = 0; nt < NTW; nt++)
#pragma unroll
            for (int j = 0; j < 4; j++) D[mi][nt][j] = 0.f;
#pragma unroll 8
    for (int g8 = 0; g8 < G8; g8++) {
        u32 a[3][4], b[4][2];
#pragma unroll
        for (int mi = 0; mi < 3; mi++)
            ldA(a[mi], pAf + 16 * mi * SXA + 8 * g8, SXA);
        for (int nt = 0; nt < NTW; nt++) {
            ldB(b[nt], Ws + (CG * ng + 8 * nt + gq) * SXA + 2 * tq + 8 * g8);
#pragma unroll
            for (int mi = 0; mi < 3; mi++) mma8(D[mi][nt], a[mi], b[nt]);
        }
    }
    for (int nt = 0; nt < NTW; nt++) {
        int col = CG * ng + 8 * nt + 2 * tq;
#pragma unroll
        for (int mi = 0; mi < 3; mi++) {
            int r0 = node0 + MB + 16 * mi + gq;
            if (r0 < nN) {
                float v0 = D[mi][nt][0] + sxv[mi][nt][0].x;
                float v1 = D[mi][nt][1] + sxv[mi][nt][0].y;
                if (RELU) { v0 = fmaxf(v0, 0.f); v1 = fmaxf(v1, 0.f); }
                fout[r0 * DOUT + col] = v0; fout[r0 * DOUT + col + 1] = v1;
            }
            if (r0 + 8 < nN) {
                float v2 = D[mi][nt][2] + sxv[mi][nt][1].x;
                float v3 = D[mi][nt][3] + sxv[mi][nt][1].y;
                if (RELU) { v2 = fmaxf(v2, 0.f); v3 = fmaxf(v3, 0.f); }
                fout[(r0 + 8) * DOUT + col] = v2; fout[(r0 + 8) * DOUT + col + 1] = v3;
            }
        }
    }
}

extern "C" void kernel_launch(void* const* d_in, const int* in_sizes, int n_in,
                              void* d_out, int out_size) {
    const float* p  = (const float*)d_in[0];
    const int* nidx = (const int*)d_in[1];
    int nN = in_sizes[1] / KNB;

    float *fA, *fB, *gX, *Wp, *Wq;
    cudaGetSymbolAddress((void**)&fA, g_fA);
    cudaGetSymbolAddress((void**)&fB, g_fB);
    cudaGetSymbolAddress((void**)&gX, g_gX);
    cudaGetSymbolAddress((void**)&Wp, g_Wp);
    cudaGetSymbolAddress((void**)&Wq, g_Wq);

    auto smPre = [](int DIN, int DOUT) {
        return ((144 + 256) * (DIN + 8) + 4 * DIN + DOUT) * 4;
    };
    auto smRec = [](int DIN) {
        int NXB = (DIN == 64) ? 2 : 1;
        return (NXB * 144 * (DIN + 8) + 2 * 128 * (DIN + 8)) * 4;
    };
    cudaFuncSetAttribute(pre_k<64, 128>,  cudaFuncAttributeMaxDynamicSharedMemorySize, smPre(64, 128));
    cudaFuncSetAttribute(pre_k<128, 128>, cudaFuncAttributeMaxDynamicSharedMemorySize, smPre(128, 128));
    cudaFuncSetAttribute(pre_k<128, 32>,  cudaFuncAttributeMaxDynamicSharedMemorySize, smPre(128, 32));
    cudaFuncSetAttribute(rec_k<64, 128, true>,  cudaFuncAttributeMaxDynamicSharedMemorySize, smRec(64));
    cudaFuncSetAttribute(rec_k<128, 128, true>, cudaFuncAttributeMaxDynamicSharedMemorySize, smRec(128));
    cudaFuncSetAttribute(rec_k<128, 32, false>, cudaFuncAttributeMaxDynamicSharedMemorySize, smRec(128));

    build_feat0<<<(nN * 64 + 255) / 256, 256>>>(p, fA, nN);

    int grid = (nN + 143) / 144;
    // layer 0
    pack_all<<<((384 + 256) * 64 + 255) / 256, 256>>>(
        (const float*)d_in[2], (const float*)d_in[3], (const float*)d_in[6], Wq, Wp, 64, 128);
    pre_k<64, 128><<<grid, 384, smPre(64, 128)>>>(
        fA, Wq, (const float*)d_in[4], (const float*)d_in[5],
        (const float*)d_in[8], gX, nN);
    rec_k<64, 128, true><<<grid, 384, smRec(64)>>>(
        gX, nidx, Wp, (const float*)d_in[7], fB, nN);
    // layer 1
    pack_all<<<((640 + 512) * 128 + 255) / 256, 256>>>(
        (const float*)d_in[9], (const float*)d_in[10], (const float*)d_in[13], Wq, Wp, 128, 128);
    pre_k<128, 128><<<grid, 384, smPre(128, 128)>>>(
        fB, Wq, (const float*)d_in[11], (const float*)d_in[12],
        (const float*)d_in[15], gX, nN);
    rec_k<128, 128, true><<<grid, 384, smRec(128)>>>(
        gX, nidx, Wp, (const float*)d_in[14], fA, nN);
    // layer 2
    pack_all<<<((544 + 512) * 128 + 255) / 256, 256>>>(
        (const float*)d_in[16], (const float*)d_in[17], (const float*)d_in[20], Wq, Wp, 128, 32);
    pre_k<128, 32><<<grid, 384, smPre(128, 32)>>>(
        fA, Wq, (const float*)d_in[18], (const float*)d_in[19],
        (const float*)d_in[22], gX, nN);
    rec_k<128, 32, false><<<grid, 384, smRec(128)>>>(
        gX, nidx, Wp, (const float*)d_in[21], (float*)d_out, nN);
}

// round 17
// speedup vs baseline: 1.1474x; 1.0016x over previous
#include <cuda_runtime.h>
#define KNB 16
typedef unsigned u32;

__device__ __align__(256) float g_fA[20096 * 128];
__device__ __align__(256) float g_fB[20096 * 128];
__device__ __align__(256) float g_gX[20096 * 640];
__device__ __align__(256) float g_Wp[512 * 128];
__device__ __align__(256) float g_Wq[640 * 128];

__device__ __forceinline__ float tanha(float x) {
    float r; asm("tanh.approx.f32 %0, %1;" : "=f"(r) : "f"(x)); return r;
}
__device__ __forceinline__ float siga(float x) {
    return fmaf(tanha(0.5f * x), 0.5f, 0.5f);
}
__device__ __forceinline__ u32 tf32r(float f) {
    u32 r; asm("cvt.rna.tf32.f32 %0, %1;" : "=r"(r) : "f"(f)); return r;
}
__device__ __forceinline__ uint4 tf32x4(float4 v) {
    return make_uint4(tf32r(v.x), tf32r(v.y), tf32r(v.z), tf32r(v.w));
}
__device__ __forceinline__ void mma8(float* d, const u32* a, const u32* b) {
    asm volatile("mma.sync.aligned.m16n8k8.row.col.f32.tf32.tf32.f32 "
        "{%0,%1,%2,%3},{%4,%5,%6,%7},{%8,%9},{%0,%1,%2,%3};"
        : "+f"(d[0]), "+f"(d[1]), "+f"(d[2]), "+f"(d[3])
        : "r"(a[0]), "r"(a[1]), "r"(a[2]), "r"(a[3]), "r"(b[0]), "r"(b[1]));
}
__device__ __forceinline__ u32 smem_u32(const void* p) {
    u32 a; asm("{ .reg .u64 t; cvta.to.shared.u64 t, %1; cvt.u32.u64 %0, t; }" : "=r"(a) : "l"(p)); return a;
}
__device__ __forceinline__ void cpa16(u32 dst, const void* src) {
    asm volatile("cp.async.cg.shared.global [%0], [%1], 16;" :: "r"(dst), "l"(src));
}
__device__ __forceinline__ void cpa_commit() { asm volatile("cp.async.commit_group;"); }
__device__ __forceinline__ void cpa_wait0()  { asm volatile("cp.async.wait_group 0;" ::: "memory"); }

// Gate-column permutation (see R10): thread (gq,tq) of warp ng owns all 4 gates
// of its units directly in its MMA output registers.
__device__ __forceinline__ int gmap(int c, int DIN) {
    int blk = c >> 5, w5 = c & 31;
    int nt = w5 >> 3, tq = (w5 >> 1) & 3, e = w5 & 1;
    return (2 * (nt & 1) + e) * DIN + blk * 8 + (nt >> 1) * 4 + tq;
}
// k-interleave within each 8-col group: [k0,k4,k1,k5,k2,k6,k3,k7]
__device__ __forceinline__ int ilk(int k) {
    return (k & ~7) + ((k & 3) << 1) + ((k >> 2) & 1);
}
__device__ __forceinline__ void ilsh(uint4 A, uint4 B, uint4& o0, uint4& o1) {
    o0 = make_uint4(A.x, B.x, A.y, B.y);
    o1 = make_uint4(A.z, B.z, A.w, B.w);
}
// A-fragment loader: 2x LDS.64 per m-tile
__device__ __forceinline__ void ldA(u32* a, const float* pa, int SXA) {
    float2 lo = *(const float2*)pa;
    float2 hi = *(const float2*)(pa + 8 * SXA);
    a[0] = __float_as_uint(lo.x); a[1] = __float_as_uint(hi.x);
    a[2] = __float_as_uint(lo.y); a[3] = __float_as_uint(hi.y);
}
__device__ __forceinline__ void ldB(u32* b, const float* pb) {
    float2 v = *(const float2*)pb;
    b[0] = __float_as_uint(v.x); b[1] = __float_as_uint(v.y);
}

__global__ void build_feat0(const float* __restrict__ p, float* __restrict__ f0, int nN) {
    int i = blockIdx.x * blockDim.x + threadIdx.x;
    if (i >= nN * 64) return;
    int node = i >> 6, k = i & 63;
    f0[i] = (k == 0) ? (16.0f / (float)nN) : p[node * 63 + (k - 1)];
}

// merged pack: Wq = [Wih(gmap)|Wself] tf32+ilk ; Wp = Whh(gmap) tf32+ilk
__global__ void pack_all(const float* __restrict__ Wih, const float* __restrict__ Whh,
                         const float* __restrict__ Wself,
                         float* __restrict__ Wq, float* __restrict__ Wp,
                         int DIN, int DOUT) {
    int Wn = 4 * DIN + DOUT;
    int tot = (Wn + 4 * DIN) * DIN;
    int e = blockIdx.x * 256 + threadIdx.x;
    if (e >= tot) return;
    int row = e / DIN, kk = e % DIN;
    if (row < Wn) {
        float v = (row < 4 * DIN) ? Wih[gmap(row, DIN) * DIN + kk]
                                  : Wself[(row - 4 * DIN) * DIN + kk];
        Wq[row * DIN + ilk(kk)] = __uint_as_float(tf32r(v));
    } else {
        int r2 = row - Wn;
        Wp[r2 * DIN + ilk(kk)] = __uint_as_float(tf32r(Whh[gmap(r2, DIN) * DIN + kk]));
    }
}

// ---------------- precompute: gX[n] = feat[n] @ [Wih(permuted) | Wself]^T + bias ----------------
template <int DIN, int DOUT>
__global__ __launch_bounds__(384, 1)
void pre_k(const float* __restrict__ feat, const float* __restrict__ Wq,
           const float* __restrict__ bih, const float* __restrict__ bhh,
           const float* __restrict__ bo, float* __restrict__ gX, int nN)
{
    constexpr int TM = 144, NT = 384, K4 = DIN / 4, G8 = DIN / 8;
    constexpr int SXA = DIN + 8, W = 4 * DIN + DOUT;
    constexpr int NCHG = (4 * DIN) / 128;
    extern __shared__ float sm[];
    float* Xs = sm;
    float* Wb[2] = { sm + TM * SXA, sm + TM * SXA + 128 * SXA };
    float* CB = sm + (TM + 256) * SXA;

    const int tid = threadIdx.x, lane = tid & 31, w = tid >> 5;
    const int gq = lane >> 2, tq = lane & 3, mg = w % 3, ng = w / 3, MB = 48 * mg;
    const int node0 = blockIdx.x * TM;
    const u32 WbU[2] = { smem_u32(Wb[0]), smem_u32(Wb[1]) };
    const float4* fin4 = (const float4*)feat;

    for (int e = tid; e < 4 * DIN; e += NT) {
        int sr = gmap(e, DIN);
        CB[e] = bih[sr] + bhh[sr];
    }
    for (int e = tid; e < DOUT; e += NT) CB[4 * DIN + e] = bo[e];
    for (int e = tid; e < TM * G8; e += NT) {
        int row = e / G8, g8 = e % G8;
        int nd = node0 + row; if (nd >= nN) nd = nN - 1;
        uint4 A = tf32x4(fin4[nd * K4 + 2 * g8]);
        uint4 B = tf32x4(fin4[nd * K4 + 2 * g8 + 1]);
        uint4 o0, o1; ilsh(A, B, o0, o1);
        ((uint4*)(Xs + row * SXA + 8 * g8))[0] = o0;
        ((uint4*)(Xs + row * SXA + 8 * g8))[1] = o1;
    }
    {
        int CR0 = (W < 128) ? W : 128;
        for (int e = tid; e < CR0 * K4; e += NT) {
            int r = e / K4, c4 = e % K4;
            cpa16(WbU[0] + (u32)(r * SXA + c4 * 4) * 4u, Wq + r * DIN + c4 * 4);
        }
        cpa_commit();
    }
    const float* pA0 = Xs + (MB + gq) * SXA + 2 * tq;

    for (int c0 = 0; c0 < W; c0 += 128) {
        const int CR = (W - c0 < 128) ? (W - c0) : 128;
        const int NTW = CR / 32, CG = CR / 4;
        const int bi = (c0 >> 7) & 1;
        cpa_wait0();
        __syncthreads();
        if (c0 + 128 < W) {
            int CRn = (W - c0 - 128 < 128) ? (W - c0 - 128) : 128;
            const float* src = Wq + (c0 + 128) * DIN;
            for (int e = tid; e < CRn * K4; e += NT) {
                int r = e / K4, c4 = e % K4;
                cpa16(WbU[1 - bi] + (u32)(r * SXA + c4 * 4) * 4u, src + r * DIN + c4 * 4);
            }
            cpa_commit();
        }
        float D[3][4][4];
        for (int nt = 0; nt < NTW; nt++) {
            float b0 = CB[c0 + CG * ng + 8 * nt + 2 * tq];
            float b1 = CB[c0 + CG * ng + 8 * nt + 2 * tq + 1];
#pragma unroll
            for (int mi = 0; mi < 3; mi++) {
                D[mi][nt][0] = b0; D[mi][nt][1] = b1;
                D[mi][nt][2] = b0; D[mi][nt][3] = b1;
            }
        }
#pragma unroll 8
        for (int g8 = 0; g8 < G8; g8++) {
            u32 a[3][4], b[4][2];
#pragma unroll
            for (int mi = 0; mi < 3; mi++)
                ldA(a[mi], pA0 + 16 * mi * SXA + 8 * g8, SXA);
            for (int nt = 0; nt < NTW; nt++) {
                ldB(b[nt], Wb[bi] + (CG * ng + 8 * nt + gq) * SXA + 2 * tq + 8 * g8);
#pragma unroll
                for (int mi = 0; mi < 3; mi++) mma8(D[mi][nt], a[mi], b[nt]);
            }
        }
        if (c0 < 4 * DIN) {
            int ci = c0 >> 7;
            int colb = ng * (NCHG * 32) + ci * 32 + tq * 8;
#pragma unroll
            for (int mi = 0; mi < 3; mi++) {
                int r0 = node0 + MB + 16 * mi + gq;
                if (r0 < nN) {
                    *(float4*)(gX + (size_t)r0 * W + colb) =
                        make_float4(D[mi][0][0], D[mi][0][1], D[mi][1][0], D[mi][1][1]);
                    *(float4*)(gX + (size_t)r0 * W + colb + 4) =
                        make_float4(D[mi][2][0], D[mi][2][1], D[mi][3][0], D[mi][3][1]);
                }
                if (r0 + 8 < nN) {
                    *(float4*)(gX + (size_t)(r0 + 8) * W + colb) =
                        make_float4(D[mi][0][2], D[mi][0][3], D[mi][1][2], D[mi][1][3]);
                    *(float4*)(gX + (size_t)(r0 + 8) * W + colb + 4) =
                        make_float4(D[mi][2][2], D[mi][2][3], D[mi][3][2], D[mi][3][3]);
                }
            }
        } else {
            for (int nt = 0; nt < NTW; nt++) {
                int col = c0 + CG * ng + 8 * nt + 2 * tq;
#pragma unroll
                for (int mi = 0; mi < 3; mi++) {
                    int r0 = node0 + MB + 16 * mi + gq;
                    if (r0 < nN) {
                        gX[(size_t)r0 * W + col] = D[mi][nt][0];
                        gX[(size_t)r0 * W + col + 1] = D[mi][nt][1];
                    }
                    if (r0 + 8 < nN) {
                        gX[(size_t)(r0 + 8) * W + col] = D[mi][nt][2];
                        gX[(size_t)(r0 + 8) * W + col + 1] = D[mi][nt][3];
                    }
                }
            }
        }
    }
}

// ---------------- recurrent ----------------
// NCHG==2 (DIN=64): Xs double-buffered + both Whh chunks resident, 1 barrier/t.
//   Warp-rotated chunk order: odd-ng warps do chunk 1 first -> LDS/MMA and
//   MUFU/FMA phases overlap across warps instead of lock-stepping.
// NCHG==4 (DIN=128): single Xs + h_loc, cp.async double-buffered chunk pipeline.
template <int DIN, int DOUT, bool RELU>
__global__ __launch_bounds__(384, 1)
void rec_k(const float* __restrict__ gX, const int* __restrict__ nidx,
           const float* __restrict__ Wp, const float* __restrict__ Wneigh,
           float* __restrict__ fout, int nN)
{
    constexpr int TM = 144, NT = 384, K4 = DIN / 4, G8 = DIN / 8, SXA = DIN + 8;
    constexpr int W = 4 * DIN + DOUT, NCHG = (4 * DIN) / 128;
    constexpr int NXB = (NCHG <= 2) ? 2 : 1;
    extern __shared__ float sm[];
    float* XsB[2] = { sm, sm + (NXB - 1) * TM * SXA };
    float* WbBase = sm + NXB * TM * SXA;
    float* Wb[2] = { WbBase, WbBase + 128 * SXA };

    const int tid = threadIdx.x, lane = tid & 31, w = tid >> 5;
    const int gq = lane >> 2, tq = lane & 3, mg = w % 3, ng = w / 3, MB = 48 * mg;
    const int node0 = blockIdx.x * TM;
    const u32 WbU[2] = { smem_u32(Wb[0]), smem_u32(Wb[1]) };
    const float4* Wn4 = (const float4*)Wneigh;

    float c_loc[NCHG * 12], h_loc[NCHG * 12];
#pragma unroll
    for (int i = 0; i < NCHG * 12; i++) c_loc[i] = 0.f;

    if (NCHG <= 2) {
        for (int c = 0; c < NCHG; c++) {
            const float* src = Wp + c * 128 * DIN;
            for (int e = tid; e < 128 * K4; e += NT) {
                int row = e / K4, c4 = e % K4;
                cpa16(WbU[c] + (u32)(row * SXA + c4 * 4) * 4u, src + row * DIN + c4 * 4);
            }
        }
        cpa_commit();
        cpa_wait0();
        __syncthreads();
    } else {
        const float* src = Wp;
        for (int e = tid; e < 128 * K4; e += NT) {
            int row = e / K4, c4 = e % K4;
            cpa16(WbU[0] + (u32)(row * SXA + c4 * 4) * 4u, src + row * DIN + c4 * 4);
        }
        cpa_commit();
    }

    for (int t = 0; t < KNB; t++) {
        int srcs[6];
#pragma unroll
        for (int mi = 0; mi < 3; mi++)
#pragma unroll
            for (int r2 = 0; r2 < 2; r2++) {
                int nd = node0 + MB + 16 * mi + gq + 8 * r2;
                if (nd >= nN) nd = nN - 1;
                srcs[mi * 2 + r2] = nidx[nd * KNB + t];
            }
        const float* Xc = XsB[t & (NXB - 1)];
        float* Xn = XsB[(t + 1) & (NXB - 1)];
        const float* pA0 = Xc + (MB + gq) * SXA + 2 * tq;

#pragma unroll 1
        for (int cc = 0; cc < NCHG; cc++) {
            // NCHG==2: rotate chunk order by warp parity (phase mixing);
            // NCHG==4: in-order (staging pipeline requires it).
            const int ci = (NCHG <= 2) ? ((cc + (ng & 1)) % NCHG) : cc;
            float4 ga[6], gb[6];
#pragma unroll
            for (int i = 0; i < 6; i++) {
                const float4* g4 = (const float4*)(gX +
                    (size_t)srcs[i] * W + (size_t)(ng * NCHG + ci) * 32 + tq * 8);
                ga[i] = g4[0];
                gb[i] = g4[1];
            }
            if (NCHG > 2 && t > 0) {
                cpa_wait0();
                __syncthreads();
                int cn = (ci + 1 < NCHG) ? ci + 1 : 0;
                const float* src = Wp + cn * 128 * DIN;
                u32 dstU = WbU[(ci + 1) & 1];
                for (int e = tid; e < 128 * K4; e += NT) {
                    int row = e / K4, c4 = e % K4;
                    cpa16(dstU + (u32)(row * SXA + c4 * 4) * 4u, src + row * DIN + c4 * 4);
                }
                cpa_commit();
            }
            float D[3][4][4];
#pragma unroll
            for (int mi = 0; mi < 3; mi++)
#pragma unroll
                for (int nt = 0; nt < 4; nt++)
#pragma unroll
                    for (int j = 0; j < 4; j++) D[mi][nt][j] = 0.f;
            if (t > 0) {
                const float* Wc = Wb[(NCHG > 2) ? (ci & 1) : ci];
#pragma unroll 8
                for (int g8 = 0; g8 < G8; g8++) {
                    u32 a[3][4], b[4][2];
#pragma unroll
                    for (int mi = 0; mi < 3; mi++)
                        ldA(a[mi], pA0 + 16 * mi * SXA + 8 * g8, SXA);
#pragma unroll
                    for (int nt = 0; nt < 4; nt++) {
                        ldB(b[nt], Wc + (32 * ng + 8 * nt + gq) * SXA + 2 * tq + 8 * g8);
#pragma unroll
                        for (int mi = 0; mi < 3; mi++) mma8(D[mi][nt], a[mi], b[nt]);
                    }
                }
            }
            // epilogue: both 'up' cells of a (mi,r2) pair together -> paired h store
#pragma unroll
            for (int mi = 0; mi < 3; mi++)
#pragma unroll
                for (int r2 = 0; r2 < 2; r2++) {
                    int i = mi * 2 + r2;
                    float gi0 = D[mi][0][2 * r2]     + ga[i].x;
                    float gf0 = D[mi][0][2 * r2 + 1] + ga[i].y;
                    float gg0 = D[mi][1][2 * r2]     + ga[i].z;
                    float go0 = D[mi][1][2 * r2 + 1] + ga[i].w;
                    float gi1 = D[mi][2][2 * r2]     + gb[i].x;
                    float gf1 = D[mi][2][2 * r2 + 1] + gb[i].y;
                    float gg1 = D[mi][3][2 * r2]     + gb[i].z;
                    float go1 = D[mi][3][2 * r2 + 1] + gb[i].w;
                    int s0 = ci * 12 + (mi * 2 + 0) * 2 + r2;
                    int s1 = ci * 12 + (mi * 2 + 1) * 2 + r2;
                    float cc0 = siga(gf0) * c_loc[s0] + siga(gi0) * tanha(gg0);
                    float cc1 = siga(gf1) * c_loc[s1] + siga(gi1) * tanha(gg1);
                    c_loc[s0] = cc0;
                    c_loc[s1] = cc1;
                    float hv0 = __uint_as_float(tf32r(siga(go0) * tanha(cc0)));
                    float hv1 = __uint_as_float(tf32r(siga(go1) * tanha(cc1)));
                    if (NCHG <= 2) {
                        *(float2*)(Xn + (MB + 16 * mi + gq + 8 * r2) * SXA +
                                   (4 * ci + ng) * 8 + 2 * tq) = make_float2(hv0, hv1);
                    } else {
                        h_loc[s0] = hv0;
                        h_loc[s1] = hv1;
                    }
                }
        }
        if (NCHG <= 2) {
            __syncthreads();   // Xn complete; Xc reads done -> flip
        } else {
            __syncthreads();
#pragma unroll 1
            for (int ci = 0; ci < NCHG; ci++)
#pragma unroll
                for (int mi = 0; mi < 3; mi++)
#pragma unroll
                    for (int r2 = 0; r2 < 2; r2++) {
                        int s0 = ci * 12 + (mi * 2 + 0) * 2 + r2;
                        int s1 = ci * 12 + (mi * 2 + 1) * 2 + r2;
                        *(float2*)((float*)XsB[0] +
                                   (MB + 16 * mi + gq + 8 * r2) * SXA +
                                   (4 * ci + ng) * 8 + 2 * tq) =
                            make_float2(h_loc[s0], h_loc[s1]);
                    }
        }
    }

    // ---- FC: out = selfX (precomputed, bias folded) + h_final @ Wneigh^T ----
    constexpr int NTW = DOUT / 32, CG = DOUT / 4;
    const float* Xf = XsB[KNB & (NXB - 1)];
    cpa_wait0();
    __syncthreads();
    float* Ws = Wb[0];
    for (int e = tid; e < DOUT * G8; e += NT) {
        int r = e / G8, g8 = e % G8;
        uint4 A = tf32x4(Wn4[r * K4 + 2 * g8]);
        uint4 B = tf32x4(Wn4[r * K4 + 2 * g8 + 1]);
        uint4 o0, o1; ilsh(A, B, o0, o1);
        ((uint4*)(Ws + r * SXA + 8 * g8))[0] = o0;
        ((uint4*)(Ws + r * SXA + 8 * g8))[1] = o1;
    }
    __syncthreads();
    const float* pAf = Xf + (MB + gq) * SXA + 2 * tq;
    float2 sxv[3][4][2];
#pragma unroll
    for (int mi = 0; mi < 3; mi++)
#pragma unroll
        for (int r2 = 0; r2 < 2; r2++) {
            int nd = node0 + MB + 16 * mi + gq + 8 * r2;
            if (nd >= nN) nd = nN - 1;
            const float2* g2 = (const float2*)(gX +
                (size_t)nd * W + 4 * DIN + CG * ng + 2 * tq);
            for (int nt = 0; nt < NTW; nt++) sxv[mi][nt][r2] = g2[4 * nt];
        }
    float D[3][4][4];
#pragma unroll
    for (int mi = 0; mi < 3; mi++)
        for (int nt = 0; nt < NTW; nt++)
#pragma unroll
            for (int j = 0; j < 4; j++) D[mi][nt][j] = 0.f;
#pragma unroll 8
    for (int g8 = 0; g8 < G8; g8++) {
        u32 a[3][4], b[4][2];
#pragma unroll
        for (int mi = 0; mi < 3; mi++)
            ldA(a[mi], pAf + 16 * mi * SXA + 8 * g8, SXA);
        for (int nt = 0; nt < NTW; nt++) {
            ldB(b[nt], Ws + (CG * ng + 8 * nt + gq) * SXA + 2 * tq + 8 * g8);
#pragma unroll
            for (int mi = 0; mi < 3; mi++) mma8(D[mi][nt], a[mi], b[nt]);
        }
    }
    for (int nt = 0; nt < NTW; nt++) {
        int col = CG * ng + 8 * nt + 2 * tq;
#pragma unroll
        for (int mi = 0; mi < 3; mi++) {
            int r0 = node0 + MB + 16 * mi + gq;
            if (r0 < nN) {
                float v0 = D[mi][nt][0] + sxv[mi][nt][0].x;
                float v1 = D[mi][nt][1] + sxv[mi][nt][0].y;
                if (RELU) { v0 = fmaxf(v0, 0.f); v1 = fmaxf(v1, 0.f); }
                fout[r0 * DOUT + col] = v0; fout[r0 * DOUT + col + 1] = v1;
            }
            if (r0 + 8 < nN) {
                float v2 = D[mi][nt][2] + sxv[mi][nt][1].x;
                float v3 = D[mi][nt][3] + sxv[mi][nt][1].y;
                if (RELU) { v2 = fmaxf(v2, 0.f); v3 = fmaxf(v3, 0.f); }
                fout[(r0 + 8) * DOUT + col] = v2; fout[(r0 + 8) * DOUT + col + 1] = v3;
            }
        }
    }
}

extern "C" void kernel_launch(void* const* d_in, const int* in_sizes, int n_in,
                              void* d_out, int out_size) {
    const float* p  = (const float*)d_in[0];
    const int* nidx = (const int*)d_in[1];
    int nN = in_sizes[1] / KNB;

    float *fA, *fB, *gX, *Wp, *Wq;
    cudaGetSymbolAddress((void**)&fA, g_fA);
    cudaGetSymbolAddress((void**)&fB, g_fB);
    cudaGetSymbolAddress((void**)&gX, g_gX);
    cudaGetSymbolAddress((void**)&Wp, g_Wp);
    cudaGetSymbolAddress((void**)&Wq, g_Wq);

    auto smPre = [](int DIN, int DOUT) {
        return ((144 + 256) * (DIN + 8) + 4 * DIN + DOUT) * 4;
    };
    auto smRec = [](int DIN) {
        int NXB = (DIN == 64) ? 2 : 1;
        return (NXB * 144 * (DIN + 8) + 2 * 128 * (DIN + 8)) * 4;
    };
    cudaFuncSetAttribute(pre_k<64, 128>,  cudaFuncAttributeMaxDynamicSharedMemorySize, smPre(64, 128));
    cudaFuncSetAttribute(pre_k<128, 128>, cudaFuncAttributeMaxDynamicSharedMemorySize, smPre(128, 128));
    cudaFuncSetAttribute(pre_k<128, 32>,  cudaFuncAttributeMaxDynamicSharedMemorySize, smPre(128, 32));
    cudaFuncSetAttribute(rec_k<64, 128, true>,  cudaFuncAttributeMaxDynamicSharedMemorySize, smRec(64));
    cudaFuncSetAttribute(rec_k<128, 128, true>, cudaFuncAttributeMaxDynamicSharedMemorySize, smRec(128));
    cudaFuncSetAttribute(rec_k<128, 32, false>, cudaFuncAttributeMaxDynamicSharedMemorySize, smRec(128));

    build_feat0<<<(nN * 64 + 255) / 256, 256>>>(p, fA, nN);

    int grid = (nN + 143) / 144;
    // layer 0
    pack_all<<<((384 + 256) * 64 + 255) / 256, 256>>>(
        (const float*)d_in[2], (const float*)d_in[3], (const float*)d_in[6], Wq, Wp, 64, 128);
    pre_k<64, 128><<<grid, 384, smPre(64, 128)>>>(
        fA, Wq, (const float*)d_in[4], (const float*)d_in[5],
        (const float*)d_in[8], gX, nN);
    rec_k<64, 128, true><<<grid, 384, smRec(64)>>>(
        gX, nidx, Wp, (const float*)d_in[7], fB, nN);
    // layer 1
    pack_all<<<((640 + 512) * 128 + 255) / 256, 256>>>(
        (const float*)d_in[9], (const float*)d_in[10], (const float*)d_in[13], Wq, Wp, 128, 128);
    pre_k<128, 128><<<grid, 384, smPre(128, 128)>>>(
        fB, Wq, (const float*)d_in[11], (const float*)d_in[12],
        (const float*)d_in[15], gX, nN);
    rec_k<128, 128, true><<<grid, 384, smRec(128)>>>(
        gX, nidx, Wp, (const float*)d_in[14], fA, nN);
    // layer 2
    pack_all<<<((544 + 512) * 128 + 255) / 256, 256>>>(
        (const float*)d_in[16], (const float*)d_in[17], (const float*)d_in[20], Wq, Wp, 128, 32);
    pre_k<128, 32><<<grid, 384, smPre(128, 32)>>>(
        fA, Wq, (const float*)d_in[18], (const float*)d_in[19],
        (const float*)d_in[22], gX, nN);
    rec_k<128, 32, false><<<grid, 384, smRec(128)>>>(
        gX, nidx, Wp, (const float*)d_in[21], (float*)d_out, nN);
}